// round 8
// baseline (speedup 1.0000x reference)
#include <cuda_runtime.h>
#include <cuda_bf16.h>
#include <mma.h>
#include <math.h>

using namespace nvcuda;

// Problem constants
#define BB 256
#define TT 30
#define ML 31
#define VV 10000
#define HH 512
#define G4 2048            // 4*H
#define NROWS 7680         // TT*BB
#define BKB 64             // K-chunk (bf16 elems)
#define LDAB 72            // shared lda in bf16 elems (64 + 8 pad) -> 144B rows
#define LDC 132            // shared C ld (floats, 128 + 4 pad)
#define LDC2 68            // shared C ld for 64-wide tiles
#define BUFB (128 * LDAB)  // bf16 elems per A stage buffer (9216)
#define BUFB2 (64 * LDAB)  // bf16 elems per B stage buffer in k_steps (4608)
#define NSTG 3             // pipeline stages
#define DSMEM_BYTES (NSTG * 2 * BUFB * 2)          // 110592 B (128x128 GEMMs)
#define DSMEM_STEPS (NSTG * (BUFB + BUFB2) * 2)    // 82944 B (k_steps)
#define GRPBLK 32          // blocks per barrier group in k_steps

typedef __nv_bfloat16 bf16;

// ---------------- device scratch ----------------
__device__ int   g_order[BB];
__device__ int   g_declen[BB];
__device__ int   g_cnt[TT];
__device__ int   g_rowmap[NROWS];   // packed active row -> t*256+b
__device__ int   g_ntot;            // number of active rows
__device__ float g_gp[BB * G4];
__device__ float g_xp[(size_t)NROWS * G4];       // emb-proj + gp + biases (pre-folded)
__device__ float g_cc[BB * HH];
__device__ float g_rowsum[NROWS];
__device__ int   g_barcnt2[2];
__device__ int   g_barflag2[2];
// bf16 operand copies
__device__ bf16  g_Wih_bf[G4 * 1024];
__device__ bf16  g_Whh_bf[G4 * HH];
__device__ bf16  g_Wout_bf[VV * HH];
__device__ bf16  g_emb_bf[VV * HH];
__device__ bf16  g_gimg_bf[BB * HH];
__device__ bf16  g_hbuf_bf[2][BB * HH];
__device__ bf16  g_hall_bf[(size_t)NROWS * HH];

typedef wmma::fragment<wmma::matrix_a, 16, 16, 16, bf16, wmma::row_major> FragA;
typedef wmma::fragment<wmma::matrix_b, 16, 16, 16, bf16, wmma::col_major> FragB;
typedef wmma::fragment<wmma::accumulator, 16, 16, 16, float> FragC;

__device__ __forceinline__ void cp16(void* s, const void* g) {
    unsigned d = (unsigned)__cvta_generic_to_shared(s);
    asm volatile("cp.async.cg.shared.global [%0], [%1], 16;" :: "r"(d), "l"(g));
}

// ---- 3-stage pipelined bf16 GEMM: C[128x128] += A[128x512] * B[128x512]^T ----
// One __syncthreads per K-chunk. Ends with a sync (Cs reuse is safe after).
__device__ __forceinline__ void gemm_bf16(const bf16* arow, const bf16* brow,
                                          bf16* As, bf16* Bs,
                                          FragC (&c)[2][4], int tid) {
    int wp = tid >> 5, wm = wp & 3, wn = wp >> 2;
    int srow = tid >> 1, sc = (tid & 1) * 32;    // 32 bf16 = 64 B per thread
    bf16* asd = As + srow * LDAB + sc;
    bf16* bsd = Bs + srow * LDAB + sc;
    const bf16* ag = arow + sc;
    const bf16* bg = brow + sc;
    // prologue: stages 0 and 1
    #pragma unroll
    for (int q = 0; q < 32; q += 8) { cp16(asd + q, ag + q); cp16(bsd + q, bg + q); }
    asm volatile("cp.async.commit_group;");
    #pragma unroll
    for (int q = 0; q < 32; q += 8) {
        cp16(asd + BUFB + q, ag + BKB + q);
        cp16(bsd + BUFB + q, bg + BKB + q);
    }
    asm volatile("cp.async.commit_group;");
    int buf = 0;
    #pragma unroll 1
    for (int k0 = 0; k0 < HH; k0 += BKB) {
        if (k0 + BKB < HH) asm volatile("cp.async.wait_group 1;" ::: "memory");
        else               asm volatile("cp.async.wait_group 0;" ::: "memory");
        __syncthreads();   // stage `buf` visible to all; prev compute done
        if (k0 + 2 * BKB < HH) {
            int nb = buf + 2; if (nb >= NSTG) nb -= NSTG;
            #pragma unroll
            for (int q = 0; q < 32; q += 8) {
                cp16(asd + nb * BUFB + q, ag + k0 + 2 * BKB + q);
                cp16(bsd + nb * BUFB + q, bg + k0 + 2 * BKB + q);
            }
            asm volatile("cp.async.commit_group;");
        }
        bf16* Ab = As + buf * BUFB;
        bf16* Bb = Bs + buf * BUFB;
        #pragma unroll
        for (int kk = 0; kk < BKB; kk += 16) {
            FragA a0, a1; FragB bf[4];
            wmma::load_matrix_sync(a0, &Ab[(wm * 32)      * LDAB + kk], LDAB);
            wmma::load_matrix_sync(a1, &Ab[(wm * 32 + 16) * LDAB + kk], LDAB);
            #pragma unroll
            for (int j = 0; j < 4; j++)
                wmma::load_matrix_sync(bf[j], &Bb[(wn * 64 + j * 16) * LDAB + kk], LDAB);
            #pragma unroll
            for (int j = 0; j < 4; j++) {
                wmma::mma_sync(c[0][j], a0, bf[j], c[0][j]);
                wmma::mma_sync(c[1][j], a1, bf[j], c[1][j]);
            }
        }
        buf = (buf == NSTG - 1) ? 0 : buf + 1;
    }
    __syncthreads();   // all warps done with smem before caller reuses it
}

#define FRAG_INIT(c)                                     \
    _Pragma("unroll")                                    \
    for (int i = 0; i < 2; i++)                          \
        _Pragma("unroll")                                \
        for (int j = 0; j < 4; j++) wmma::fill_fragment(c[i][j], 0.f);

#define FRAG_TO_CS(c, Cs, wm, wn)                                                  \
    _Pragma("unroll")                                                              \
    for (int i = 0; i < 2; i++)                                                    \
        _Pragma("unroll")                                                          \
        for (int j = 0; j < 4; j++)                                                \
            wmma::store_matrix_sync(&Cs[(wm * 32 + i * 16) * LDC + wn * 64 + j * 16], \
                                    c[i][j], LDC, wmma::mem_row_major);

// ---------------- fp32 -> bf16 conversion ----------------
#define N_WIH (G4 * 1024)
#define N_WHH (G4 * HH)
#define N_WOUT (VV * HH)
#define N_EMB (VV * HH)
#define N_GIMG (BB * HH)
#define N_CVT2 ((N_WIH + N_WHH + N_WOUT + N_EMB + N_GIMG) / 2)

__global__ __launch_bounds__(256) void k_cvt(const float* __restrict__ Wih,
                                             const float* __restrict__ Whh,
                                             const float* __restrict__ Wout,
                                             const float* __restrict__ emb,
                                             const float* __restrict__ gimg) {
    long long i2 = (long long)blockIdx.x * 256 + threadIdx.x;
    if (i2 >= N_CVT2) return;
    long long i = i2 * 2;
    const float* src; bf16* dst; long long off;
    if (i < N_WIH)                       { src = Wih;  dst = g_Wih_bf;  off = i; }
    else if (i < (long long)N_WIH + N_WHH) { src = Whh;  dst = g_Whh_bf;  off = i - N_WIH; }
    else if (i < (long long)N_WIH + N_WHH + N_WOUT)
                                         { src = Wout; dst = g_Wout_bf; off = i - N_WIH - N_WHH; }
    else if (i < (long long)N_WIH + N_WHH + N_WOUT + N_EMB)
                                         { src = emb;  dst = g_emb_bf;  off = i - N_WIH - N_WHH - N_WOUT; }
    else                                 { src = gimg; dst = g_gimg_bf; off = i - N_WIH - N_WHH - N_WOUT - N_EMB; }
    float2 v = *(const float2*)(src + off);
    __nv_bfloat162 o = __floats2bfloat162_rn(v.x, v.y);
    *(__nv_bfloat162*)(dst + off) = o;
}

// ---------------- prep: sort + targets + packed row map ----------------
__global__ void k_prep(const int* __restrict__ w, const int* __restrict__ cap,
                       float* __restrict__ out, long long out_size) {
    __shared__ int lens[BB];
    __shared__ int off[TT + 1];
    int i = threadIdx.x;
    lens[i] = cap[i];
    __syncthreads();
    int li = lens[i];
    int rank = 0;
    #pragma unroll 8
    for (int j = 0; j < BB; j++) {
        int lj = lens[j];
        rank += (lj > li) || (lj == li && j < i);
    }
    g_order[rank]  = i;
    g_declen[rank] = li - 1;
    __syncthreads();

    if (i < TT) {
        int c = 0;
        for (int j = 0; j < BB; j++) c += (g_declen[j] > i);
        g_cnt[i] = c;
    }
    __syncthreads();
    if (i == 0) {
        int s = 0;
        for (int t = 0; t < TT; t++) { off[t] = s; s += g_cnt[t]; }
        off[TT] = s;
        g_ntot = s;
    }
    __syncthreads();
    // packed row map (t-major)
    for (int t = 0; t < TT; t++) {
        int c = g_cnt[t];
        for (int b = i; b < c; b += 256) g_rowmap[off[t] + b] = t * 256 + b;
    }
    for (int r = off[TT] + i; r < NROWS; r += 256) g_rowmap[r] = 0;

    long long PRED = (long long)BB * ML * VV;
    if (out_size >= PRED + (long long)BB * TT + BB) {
        int src = g_order[i];
        for (int k = 0; k < TT; k++)
            out[PRED + (long long)i * TT + k] = (float)w[src * ML + k + 1];
        out[PRED + (long long)BB * TT + i] = (float)g_declen[i];
    }
}

__global__ void k_init() {
    int i = blockIdx.x * blockDim.x + threadIdx.x;
    if (i < BB * HH) {
        g_hbuf_bf[0][i] = __float2bfloat16(0.f);
        g_hbuf_bf[1][i] = __float2bfloat16(0.f);
        g_cc[i] = 0.f;
    }
    if (i < NROWS) g_rowsum[i] = 0.f;
    if (i < 2) { g_barcnt2[i] = 0; g_barflag2[i] = 0; }
}

// ---- image projection: gp[b][n] = gimg[order[b]] . W_ih[n][0:512] ----
__global__ __launch_bounds__(256, 2) void k_gproj() {
    extern __shared__ bf16 dsm[];
    int tid = threadIdx.x;
    int m0 = blockIdx.y * 128, n0 = blockIdx.x * 128;
    int srow = tid >> 1;
    int wp = tid >> 5, wm = wp & 3, wn = wp >> 2;
    const bf16* arow = g_gimg_bf + (size_t)g_order[m0 + srow] * HH;
    const bf16* brow = g_Wih_bf + (size_t)(n0 + srow) * 1024;
    FragC c[2][4];
    FRAG_INIT(c);
    gemm_bf16(arow, brow, dsm, dsm + NSTG * BUFB, c, tid);
    #pragma unroll
    for (int i = 0; i < 2; i++)
        #pragma unroll
        for (int j = 0; j < 4; j++)
            wmma::store_matrix_sync(g_gp + (size_t)(m0 + wm * 32 + i * 16) * G4
                                         + n0 + wn * 64 + j * 16,
                                    c[i][j], G4, wmma::mem_row_major);
}

// ---- packed embedding projection + fold ----
__global__ __launch_bounds__(256, 2) void k_xproj(const int* __restrict__ w,
                                                  const float* __restrict__ bih,
                                                  const float* __restrict__ bhh) {
    extern __shared__ bf16 dsm[];
    int tid = threadIdx.x;
    int m0 = blockIdx.y * 128;
    int ntot = g_ntot;
    if (m0 >= ntot) return;
    int n0 = blockIdx.x * 128;
    int srow = tid >> 1;
    int wp = tid >> 5, wm = wp & 3, wn = wp >> 2;
    int tb = g_rowmap[m0 + srow];
    int t_r = tb >> 8, b_r = tb & 255;
    int word = w[g_order[b_r] * ML + t_r];
    const bf16* arow = g_emb_bf + (size_t)word * HH;
    const bf16* brow = g_Wih_bf + (size_t)(n0 + srow) * 1024 + 512;
    FragC c[2][4];
    FRAG_INIT(c);
    gemm_bf16(arow, brow, dsm, dsm + NSTG * BUFB, c, tid);
    float* Cs = (float*)dsm;
    FRAG_TO_CS(c, Cs, wm, wn);
    __syncthreads();
    int row = tid >> 1, cb = (tid & 1) * 64;
    int r = m0 + row;
    if (r < ntot) {
        int tb2 = g_rowmap[r];
        int b = tb2 & 255;
        size_t xb = (size_t)tb2 * G4;
        #pragma unroll
        for (int q = 0; q < 16; q++) {
            int n = n0 + cb + q * 4;
            float4 cv = *(const float4*)&Cs[row * LDC + cb + q * 4];
            float4 gp = *(const float4*)(g_gp + (size_t)b * G4 + n);
            float4 b1 = *(const float4*)(bih + n);
            float4 b2 = *(const float4*)(bhh + n);
            float4 v;
            v.x = cv.x + gp.x + b1.x + b2.x;
            v.y = cv.y + gp.y + b1.y + b2.y;
            v.z = cv.z + gp.z + b1.z + b2.z;
            v.w = cv.w + gp.w + b1.w + b2.w;
            *(float4*)(g_xp + xb + n) = v;
        }
    }
}

// ---- persistent recurrent kernel: 2 groups x 32 blocks; group-local barrier,
//      group 1 exits early once cnt <= 128. C tile 128b x 64 (4 gates x 16 h).
__global__ __launch_bounds__(256) void k_steps() {
    extern __shared__ bf16 dsm[];
    bf16* As = dsm;                    // NSTG x BUFB
    bf16* Bs = dsm + NSTG * BUFB;      // NSTG x BUFB2
    float* Cs = (float*)dsm;           // reuse (128 x LDC2 floats = 34816 B)
    int tid = threadIdx.x;
    int h0 = blockIdx.x * 16;          // 32 h-tiles of 16
    int grp = blockIdx.y;              // barrier group = b-tile
    int b0 = grp * 128;
    int wp = tid >> 5, wm = wp & 3, wn = wp >> 2;
    int srowA = tid >> 1, scA = (tid & 1) * 32;
    int srowB = tid >> 2, scB = (tid & 3) * 16;
    int gate = srowB >> 4, hh_s = srowB & 15;
    const bf16* browg = g_Whh_bf + (size_t)(gate * 512 + h0 + hh_s) * HH + scB;
    bf16* asd = As + srowA * LDAB + scA;
    bf16* bsd = Bs + srowB * LDAB + scB;

    for (int t = 0; t < TT; t++) {
        int cnt = g_cnt[t];
        if (cnt <= b0) break;          // consistent across the whole group
        {
            FragC c[2][2];
            #pragma unroll
            for (int i = 0; i < 2; i++)
                #pragma unroll
                for (int j = 0; j < 2; j++) wmma::fill_fragment(c[i][j], 0.f);
            const bf16* arowg = g_hbuf_bf[t & 1] + (size_t)(b0 + srowA) * HH + scA;
            // prologue: stages 0, 1
            #pragma unroll
            for (int q = 0; q < 32; q += 8) cp16(asd + q, arowg + q);
            #pragma unroll
            for (int q = 0; q < 16; q += 8) cp16(bsd + q, browg + q);
            asm volatile("cp.async.commit_group;");
            #pragma unroll
            for (int q = 0; q < 32; q += 8) cp16(asd + BUFB + q, arowg + BKB + q);
            #pragma unroll
            for (int q = 0; q < 16; q += 8) cp16(bsd + BUFB2 + q, browg + BKB + q);
            asm volatile("cp.async.commit_group;");
            int buf = 0;
            #pragma unroll 1
            for (int k0 = 0; k0 < HH; k0 += BKB) {
                if (k0 + BKB < HH) asm volatile("cp.async.wait_group 1;" ::: "memory");
                else               asm volatile("cp.async.wait_group 0;" ::: "memory");
                __syncthreads();
                if (k0 + 2 * BKB < HH) {
                    int nb = buf + 2; if (nb >= NSTG) nb -= NSTG;
                    #pragma unroll
                    for (int q = 0; q < 32; q += 8)
                        cp16(asd + nb * BUFB + q, arowg + k0 + 2 * BKB + q);
                    #pragma unroll
                    for (int q = 0; q < 16; q += 8)
                        cp16(bsd + nb * BUFB2 + q, browg + k0 + 2 * BKB + q);
                    asm volatile("cp.async.commit_group;");
                }
                bf16* Ab = As + buf * BUFB;
                bf16* Bb = Bs + buf * BUFB2;
                #pragma unroll
                for (int kk = 0; kk < BKB; kk += 16) {
                    FragA a0, a1; FragB bf0, bf1;
                    wmma::load_matrix_sync(a0, &Ab[(wm * 32)      * LDAB + kk], LDAB);
                    wmma::load_matrix_sync(a1, &Ab[(wm * 32 + 16) * LDAB + kk], LDAB);
                    wmma::load_matrix_sync(bf0, &Bb[(wn * 32)      * LDAB + kk], LDAB);
                    wmma::load_matrix_sync(bf1, &Bb[(wn * 32 + 16) * LDAB + kk], LDAB);
                    wmma::mma_sync(c[0][0], a0, bf0, c[0][0]);
                    wmma::mma_sync(c[0][1], a0, bf1, c[0][1]);
                    wmma::mma_sync(c[1][0], a1, bf0, c[1][0]);
                    wmma::mma_sync(c[1][1], a1, bf1, c[1][1]);
                }
                buf = (buf == NSTG - 1) ? 0 : buf + 1;
            }
            __syncthreads();
            #pragma unroll
            for (int i = 0; i < 2; i++)
                #pragma unroll
                for (int j = 0; j < 2; j++)
                    wmma::store_matrix_sync(&Cs[(wm * 32 + i * 16) * LDC2 + wn * 32 + j * 16],
                                            c[i][j], LDC2, wmma::mem_row_major);
            __syncthreads();
            // LSTM elementwise: 128 b x 16 h
            #pragma unroll
            for (int it = 0; it < 8; it++) {
                int p = it * 256 + tid;        // 0..2047
                int row = p >> 4;
                int hh = p & 15;
                int b = b0 + row;
                if (b >= cnt) continue;
                size_t xpb = (size_t)(t * BB + b) * G4 + h0 + hh;
                float iv = Cs[row * LDC2 + 0  + hh] + g_xp[xpb];
                float fv = Cs[row * LDC2 + 16 + hh] + g_xp[xpb + 512];
                float gv = Cs[row * LDC2 + 32 + hh] + g_xp[xpb + 1024];
                float ov = Cs[row * LDC2 + 48 + hh] + g_xp[xpb + 1536];
                iv = 1.f / (1.f + __expf(-iv));
                fv = 1.f / (1.f + __expf(-fv));
                ov = 1.f / (1.f + __expf(-ov));
                gv = tanhf(gv);
                int hidx = b * HH + h0 + hh;
                float cn = fv * g_cc[hidx] + iv * gv;
                float hn = ov * tanhf(cn);
                g_cc[hidx] = cn;
                bf16 hb = __float2bfloat16(hn);
                g_hbuf_bf[(t + 1) & 1][hidx] = hb;
                g_hall_bf[(size_t)(t * BB + b) * HH + h0 + hh] = hb;
            }
            __syncthreads();
        }
        // group-local barrier (32 blocks)
        __threadfence();
        if (tid == 0) {
            int v = atomicAdd(&g_barcnt2[grp], 1);
            if (v == GRPBLK - 1) {
                atomicExch(&g_barcnt2[grp], 0);
                __threadfence();
                atomicExch(&g_barflag2[grp], t + 1);
            } else {
                volatile int* f = &g_barflag2[grp];
                while (*f < t + 1) {}
                __threadfence();
            }
        }
        __syncthreads();
    }
}

// ---- packed vocab projection: logits -> out + rowsum of exp ----
__global__ __launch_bounds__(256, 2) void k_out1(const float* __restrict__ bout,
                                                 float* __restrict__ out) {
    extern __shared__ bf16 dsm[];
    int tid = threadIdx.x;
    int m0 = blockIdx.y * 128;
    int ntot = g_ntot;
    if (m0 >= ntot) return;
    int n0 = blockIdx.x * 128;
    int srow = tid >> 1;
    int wp = tid >> 5, wm = wp & 3, wn = wp >> 2;
    int tb = g_rowmap[m0 + srow];
    const bf16* arow = g_hall_bf + (size_t)tb * HH;
    int nb = n0 + srow;
    const bf16* brow = g_Wout_bf + (size_t)(nb < VV ? nb : VV - 1) * HH;
    FragC c[2][4];
    FRAG_INIT(c);
    gemm_bf16(arow, brow, dsm, dsm + NSTG * BUFB, c, tid);
    float* Cs = (float*)dsm;
    FRAG_TO_CS(c, Cs, wm, wn);
    __syncthreads();

    int row = tid >> 1, cb = (tid & 1) * 64;
    int r = m0 + row;
    if (r < ntot) {
        int tb2 = g_rowmap[r];
        int t = tb2 >> 8, b = tb2 & 255;
        size_t obase = ((size_t)b * ML + t) * VV;
        float psum = 0.f;
        #pragma unroll
        for (int q = 0; q < 16; q++) {
            int n = n0 + cb + q * 4;
            if (n < VV) {
                float4 cv = *(const float4*)&Cs[row * LDC + cb + q * 4];
                float4 bo = *(const float4*)(bout + n);
                float4 v;
                v.x = cv.x + bo.x; v.y = cv.y + bo.y;
                v.z = cv.z + bo.z; v.w = cv.w + bo.w;
                *(float4*)(out + obase + n) = v;
                psum += __expf(v.x) + __expf(v.y) + __expf(v.z) + __expf(v.w);
            }
        }
        atomicAdd(&g_rowsum[tb2], psum);
    }
}

// ---- final: full-output pass; zeros inactive/pad, log-softmax for active ----
__global__ __launch_bounds__(256) void k_out2(float* __restrict__ out) {
    long long idx = (long long)blockIdx.x * 256 + threadIdx.x;
    const int perRow = VV / 4;
    const long long TOT = (long long)BB * ML * perRow;
    if (idx >= TOT) return;
    int r = (int)(idx / perRow);               // r = b*31 + t
    int v4 = (int)(idx % perRow);
    int b = r / ML, t = r - b * ML;
    size_t p = (size_t)r * VV + v4 * 4;
    bool active = (t < TT) && (b < g_cnt[t]);
    float4 o = make_float4(0.f, 0.f, 0.f, 0.f);
    if (active) {
        float ls = logf(g_rowsum[t * BB + b]);
        float4 lv = *(const float4*)(out + p);
        o.x = lv.x - ls; o.y = lv.y - ls; o.z = lv.z - ls; o.w = lv.w - ls;
    }
    *(float4*)(out + p) = o;
}

// ---------------- launch ----------------
extern "C" void kernel_launch(void* const* d_in, const int* in_sizes, int n_in,
                              void* d_out, int out_size) {
    const float* gimg = (const float*)d_in[0];
    const int*   w    = (const int*)d_in[1];
    const int*   cap  = (const int*)d_in[2];
    const float* emb  = (const float*)d_in[3];
    const float* Wih  = (const float*)d_in[4];
    const float* Whh  = (const float*)d_in[5];
    const float* bih  = (const float*)d_in[6];
    const float* bhh  = (const float*)d_in[7];
    const float* Wout = (const float*)d_in[8];
    const float* bout = (const float*)d_in[9];
    float* out = (float*)d_out;

    static int attr_done = 0;
    if (!attr_done) {
        cudaFuncSetAttribute(k_gproj, cudaFuncAttributeMaxDynamicSharedMemorySize, DSMEM_BYTES);
        cudaFuncSetAttribute(k_xproj, cudaFuncAttributeMaxDynamicSharedMemorySize, DSMEM_BYTES);
        cudaFuncSetAttribute(k_steps, cudaFuncAttributeMaxDynamicSharedMemorySize, DSMEM_STEPS);
        cudaFuncSetAttribute(k_out1,  cudaFuncAttributeMaxDynamicSharedMemorySize, DSMEM_BYTES);
        attr_done = 1;
    }

    k_cvt<<<(int)((N_CVT2 + 255) / 256), 256>>>(Wih, Whh, Wout, emb, gimg);
    k_prep<<<1, 256>>>(w, cap, out, (long long)out_size);
    k_init<<<512, 256>>>();
    k_gproj<<<dim3(16, 2), 256, DSMEM_BYTES>>>();
    k_xproj<<<dim3(16, 60), 256, DSMEM_BYTES>>>(w, bih, bhh);
    k_steps<<<dim3(32, 2), 256, DSMEM_STEPS>>>();
    k_out1<<<dim3(79, 60), 256, DSMEM_BYTES>>>(bout, out);
    long long tot = (long long)BB * ML * (VV / 4);
    k_out2<<<(int)((tot + 255) / 256), 256>>>(out);
}

// round 9
// speedup vs baseline: 1.0563x; 1.0563x over previous
#include <cuda_runtime.h>
#include <cuda_bf16.h>
#include <mma.h>
#include <math.h>

using namespace nvcuda;

// Problem constants
#define BB 256
#define TT 30
#define ML 31
#define VV 10000
#define HH 512
#define G4 2048            // 4*H
#define NROWS 7680         // TT*BB
#define BKB 64             // K-chunk (bf16 elems)
#define LDAB 72            // shared lda in bf16 elems (64 + 8 pad) -> 144B rows
#define LDC 132            // shared C ld (floats, 128 + 4 pad)
#define LDC2 68            // shared C ld for 64-wide tiles
#define BUFB (128 * LDAB)  // bf16 elems per A stage buffer (9216)
#define NSTG 3             // pipeline stages (big GEMMs)
#define DSMEM_BYTES (NSTG * 2 * BUFB * 2)          // 110592 B (128x128 GEMMs)
// k_steps: A image 8 chunks x 128 x LDAB + resident B 8 chunks x 64 x LDAB
#define ACH (128 * LDAB)   // 9216
#define BCH (64 * LDAB)    // 4608
#define NCHUNK 8
#define DSMEM_STEPS ((NCHUNK * ACH + NCHUNK * BCH) * 2)   // 221184 B
#define GRPBLK 32          // blocks per barrier group in k_steps

typedef __nv_bfloat16 bf16;

// ---------------- device scratch ----------------
__device__ int   g_order[BB];
__device__ int   g_declen[BB];
__device__ int   g_cnt[TT];
__device__ int   g_rowmap[NROWS];   // packed active row -> t*256+b
__device__ int   g_ntot;            // number of active rows
__device__ float g_gp[BB * G4];
__device__ float g_xp[(size_t)NROWS * G4];       // emb-proj + gp + biases (pre-folded)
__device__ float g_cc[BB * HH];
__device__ float g_rowsum[NROWS];
__device__ int   g_barcnt2[2];
__device__ int   g_barflag2[2];
// bf16 operand copies
__device__ bf16  g_Wih_bf[G4 * 1024];
__device__ bf16  g_Whh_bf[G4 * HH];
__device__ bf16  g_Wout_bf[VV * HH];
__device__ bf16  g_emb_bf[VV * HH];
__device__ bf16  g_gimg_bf[BB * HH];
__device__ bf16  g_hbuf_bf[2][BB * HH];
__device__ bf16  g_hall_bf[(size_t)NROWS * HH];

typedef wmma::fragment<wmma::matrix_a, 16, 16, 16, bf16, wmma::row_major> FragA;
typedef wmma::fragment<wmma::matrix_b, 16, 16, 16, bf16, wmma::col_major> FragB;
typedef wmma::fragment<wmma::accumulator, 16, 16, 16, float> FragC;

__device__ __forceinline__ void cp16(void* s, const void* g) {
    unsigned d = (unsigned)__cvta_generic_to_shared(s);
    asm volatile("cp.async.cg.shared.global [%0], [%1], 16;" :: "r"(d), "l"(g));
}

// ---- 3-stage pipelined bf16 GEMM: C[128x128] += A[128x512] * B[128x512]^T ----
__device__ __forceinline__ void gemm_bf16(const bf16* arow, const bf16* brow,
                                          bf16* As, bf16* Bs,
                                          FragC (&c)[2][4], int tid) {
    int wp = tid >> 5, wm = wp & 3, wn = wp >> 2;
    int srow = tid >> 1, sc = (tid & 1) * 32;    // 32 bf16 = 64 B per thread
    bf16* asd = As + srow * LDAB + sc;
    bf16* bsd = Bs + srow * LDAB + sc;
    const bf16* ag = arow + sc;
    const bf16* bg = brow + sc;
    #pragma unroll
    for (int q = 0; q < 32; q += 8) { cp16(asd + q, ag + q); cp16(bsd + q, bg + q); }
    asm volatile("cp.async.commit_group;");
    #pragma unroll
    for (int q = 0; q < 32; q += 8) {
        cp16(asd + BUFB + q, ag + BKB + q);
        cp16(bsd + BUFB + q, bg + BKB + q);
    }
    asm volatile("cp.async.commit_group;");
    int buf = 0;
    #pragma unroll 1
    for (int k0 = 0; k0 < HH; k0 += BKB) {
        if (k0 + BKB < HH) asm volatile("cp.async.wait_group 1;" ::: "memory");
        else               asm volatile("cp.async.wait_group 0;" ::: "memory");
        __syncthreads();
        if (k0 + 2 * BKB < HH) {
            int nb = buf + 2; if (nb >= NSTG) nb -= NSTG;
            #pragma unroll
            for (int q = 0; q < 32; q += 8) {
                cp16(asd + nb * BUFB + q, ag + k0 + 2 * BKB + q);
                cp16(bsd + nb * BUFB + q, bg + k0 + 2 * BKB + q);
            }
            asm volatile("cp.async.commit_group;");
        }
        bf16* Ab = As + buf * BUFB;
        bf16* Bb = Bs + buf * BUFB;
        #pragma unroll
        for (int kk = 0; kk < BKB; kk += 16) {
            FragA a0, a1; FragB bf[4];
            wmma::load_matrix_sync(a0, &Ab[(wm * 32)      * LDAB + kk], LDAB);
            wmma::load_matrix_sync(a1, &Ab[(wm * 32 + 16) * LDAB + kk], LDAB);
            #pragma unroll
            for (int j = 0; j < 4; j++)
                wmma::load_matrix_sync(bf[j], &Bb[(wn * 64 + j * 16) * LDAB + kk], LDAB);
            #pragma unroll
            for (int j = 0; j < 4; j++) {
                wmma::mma_sync(c[0][j], a0, bf[j], c[0][j]);
                wmma::mma_sync(c[1][j], a1, bf[j], c[1][j]);
            }
        }
        buf = (buf == NSTG - 1) ? 0 : buf + 1;
    }
    __syncthreads();
}

#define FRAG_INIT(c)                                     \
    _Pragma("unroll")                                    \
    for (int i = 0; i < 2; i++)                          \
        _Pragma("unroll")                                \
        for (int j = 0; j < 4; j++) wmma::fill_fragment(c[i][j], 0.f);

#define FRAG_TO_CS(c, Cs, wm, wn)                                                  \
    _Pragma("unroll")                                                              \
    for (int i = 0; i < 2; i++)                                                    \
        _Pragma("unroll")                                                          \
        for (int j = 0; j < 4; j++)                                                \
            wmma::store_matrix_sync(&Cs[(wm * 32 + i * 16) * LDC + wn * 64 + j * 16], \
                                    c[i][j], LDC, wmma::mem_row_major);

// ---------------- fp32 -> bf16 conversion ----------------
#define N_WIH (G4 * 1024)
#define N_WHH (G4 * HH)
#define N_WOUT (VV * HH)
#define N_EMB (VV * HH)
#define N_GIMG (BB * HH)
#define N_CVT2 ((N_WIH + N_WHH + N_WOUT + N_EMB + N_GIMG) / 2)

__global__ __launch_bounds__(256) void k_cvt(const float* __restrict__ Wih,
                                             const float* __restrict__ Whh,
                                             const float* __restrict__ Wout,
                                             const float* __restrict__ emb,
                                             const float* __restrict__ gimg) {
    long long i2 = (long long)blockIdx.x * 256 + threadIdx.x;
    if (i2 >= N_CVT2) return;
    long long i = i2 * 2;
    const float* src; bf16* dst; long long off;
    if (i < N_WIH)                       { src = Wih;  dst = g_Wih_bf;  off = i; }
    else if (i < (long long)N_WIH + N_WHH) { src = Whh;  dst = g_Whh_bf;  off = i - N_WIH; }
    else if (i < (long long)N_WIH + N_WHH + N_WOUT)
                                         { src = Wout; dst = g_Wout_bf; off = i - N_WIH - N_WHH; }
    else if (i < (long long)N_WIH + N_WHH + N_WOUT + N_EMB)
                                         { src = emb;  dst = g_emb_bf;  off = i - N_WIH - N_WHH - N_WOUT; }
    else                                 { src = gimg; dst = g_gimg_bf; off = i - N_WIH - N_WHH - N_WOUT - N_EMB; }
    float2 v = *(const float2*)(src + off);
    __nv_bfloat162 o = __floats2bfloat162_rn(v.x, v.y);
    *(__nv_bfloat162*)(dst + off) = o;
}

// ---------------- prep: sort + targets + packed row map ----------------
__global__ void k_prep(const int* __restrict__ w, const int* __restrict__ cap,
                       float* __restrict__ out, long long out_size) {
    __shared__ int lens[BB];
    __shared__ int off[TT + 1];
    int i = threadIdx.x;
    lens[i] = cap[i];
    __syncthreads();
    int li = lens[i];
    int rank = 0;
    #pragma unroll 8
    for (int j = 0; j < BB; j++) {
        int lj = lens[j];
        rank += (lj > li) || (lj == li && j < i);
    }
    g_order[rank]  = i;
    g_declen[rank] = li - 1;
    __syncthreads();

    if (i < TT) {
        int c = 0;
        for (int j = 0; j < BB; j++) c += (g_declen[j] > i);
        g_cnt[i] = c;
    }
    __syncthreads();
    if (i == 0) {
        int s = 0;
        for (int t = 0; t < TT; t++) { off[t] = s; s += g_cnt[t]; }
        off[TT] = s;
        g_ntot = s;
    }
    __syncthreads();
    for (int t = 0; t < TT; t++) {
        int c = g_cnt[t];
        for (int b = i; b < c; b += 256) g_rowmap[off[t] + b] = t * 256 + b;
    }
    for (int r = off[TT] + i; r < NROWS; r += 256) g_rowmap[r] = 0;

    long long PRED = (long long)BB * ML * VV;
    if (out_size >= PRED + (long long)BB * TT + BB) {
        int src = g_order[i];
        for (int k = 0; k < TT; k++)
            out[PRED + (long long)i * TT + k] = (float)w[src * ML + k + 1];
        out[PRED + (long long)BB * TT + i] = (float)g_declen[i];
    }
}

__global__ void k_init() {
    int i = blockIdx.x * blockDim.x + threadIdx.x;
    if (i < BB * HH) {
        g_hbuf_bf[0][i] = __float2bfloat16(0.f);
        g_hbuf_bf[1][i] = __float2bfloat16(0.f);
        g_cc[i] = 0.f;
    }
    if (i < NROWS) g_rowsum[i] = 0.f;
    if (i < 2) { g_barcnt2[i] = 0; g_barflag2[i] = 0; }
}

// ---- image projection: gp[b][n] = gimg[order[b]] . W_ih[n][0:512] ----
__global__ __launch_bounds__(256, 2) void k_gproj() {
    extern __shared__ bf16 dsm[];
    int tid = threadIdx.x;
    int m0 = blockIdx.y * 128, n0 = blockIdx.x * 128;
    int srow = tid >> 1;
    int wp = tid >> 5, wm = wp & 3, wn = wp >> 2;
    const bf16* arow = g_gimg_bf + (size_t)g_order[m0 + srow] * HH;
    const bf16* brow = g_Wih_bf + (size_t)(n0 + srow) * 1024;
    FragC c[2][4];
    FRAG_INIT(c);
    gemm_bf16(arow, brow, dsm, dsm + NSTG * BUFB, c, tid);
    #pragma unroll
    for (int i = 0; i < 2; i++)
        #pragma unroll
        for (int j = 0; j < 4; j++)
            wmma::store_matrix_sync(g_gp + (size_t)(m0 + wm * 32 + i * 16) * G4
                                         + n0 + wn * 64 + j * 16,
                                    c[i][j], G4, wmma::mem_row_major);
}

// ---- packed embedding projection + fold ----
__global__ __launch_bounds__(256, 2) void k_xproj(const int* __restrict__ w,
                                                  const float* __restrict__ bih,
                                                  const float* __restrict__ bhh) {
    extern __shared__ bf16 dsm[];
    int tid = threadIdx.x;
    int m0 = blockIdx.y * 128;
    int ntot = g_ntot;
    if (m0 >= ntot) return;
    int n0 = blockIdx.x * 128;
    int srow = tid >> 1;
    int wp = tid >> 5, wm = wp & 3, wn = wp >> 2;
    int tb = g_rowmap[m0 + srow];
    int t_r = tb >> 8, b_r = tb & 255;
    int word = w[g_order[b_r] * ML + t_r];
    const bf16* arow = g_emb_bf + (size_t)word * HH;
    const bf16* brow = g_Wih_bf + (size_t)(n0 + srow) * 1024 + 512;
    FragC c[2][4];
    FRAG_INIT(c);
    gemm_bf16(arow, brow, dsm, dsm + NSTG * BUFB, c, tid);
    float* Cs = (float*)dsm;
    FRAG_TO_CS(c, Cs, wm, wn);
    __syncthreads();
    int row = tid >> 1, cb = (tid & 1) * 64;
    int r = m0 + row;
    if (r < ntot) {
        int tb2 = g_rowmap[r];
        int b = tb2 & 255;
        size_t xb = (size_t)tb2 * G4;
        #pragma unroll
        for (int q = 0; q < 16; q++) {
            int n = n0 + cb + q * 4;
            float4 cv = *(const float4*)&Cs[row * LDC + cb + q * 4];
            float4 gp = *(const float4*)(g_gp + (size_t)b * G4 + n);
            float4 b1 = *(const float4*)(bih + n);
            float4 b2 = *(const float4*)(bhh + n);
            float4 v;
            v.x = cv.x + gp.x + b1.x + b2.x;
            v.y = cv.y + gp.y + b1.y + b2.y;
            v.z = cv.z + gp.z + b1.z + b2.z;
            v.w = cv.w + gp.w + b1.w + b2.w;
            *(float4*)(g_xp + xb + n) = v;
        }
    }
}

// ---- persistent recurrent kernel v3: resident W_hh B-tile + upfront A image.
//      2 groups x 32 blocks; per-step: 2 syncs, then uninterrupted mma burst.
__global__ __launch_bounds__(256) void k_steps() {
    extern __shared__ bf16 dsm[];
    bf16* Af = dsm;                    // NCHUNK x ACH (A image)
    bf16* Br = dsm + NCHUNK * ACH;     // NCHUNK x BCH (resident B)
    float* Cs = (float*)dsm;           // reuse A region after burst
    int tid = threadIdx.x;
    int h0 = blockIdx.x * 16;          // 32 h-tiles of 16
    int grp = blockIdx.y;
    int b0 = grp * 128;
    int wp = tid >> 5, wm = wp & 3, wn = wp >> 2;
    int srowA = tid >> 1, scA = (tid & 1) * 32;

    // ---- load resident B: W_hh rows (gate*512 + h0 + hh), chunked K layout ----
    {
        int row = tid >> 2, c16 = (tid & 3) * 16;
        int gate = row >> 4, hh_s = row & 15;
        const bf16* bg = g_Whh_bf + (size_t)(gate * 512 + h0 + hh_s) * HH;
        #pragma unroll
        for (int ch = 0; ch < NCHUNK; ch++) {
            bf16* d = Br + ch * BCH + row * LDAB + c16;
            const bf16* s = bg + ch * BKB + c16;
            cp16(d, s); cp16(d + 8, s + 8);
        }
        asm volatile("cp.async.commit_group;");
        asm volatile("cp.async.wait_group 0;" ::: "memory");
        __syncthreads();
    }

    for (int t = 0; t < TT; t++) {
        int cnt = g_cnt[t];
        if (cnt <= b0) break;          // consistent across the whole group
        FragC c[2][2];
        #pragma unroll
        for (int i = 0; i < 2; i++)
            #pragma unroll
            for (int j = 0; j < 2; j++) wmma::fill_fragment(c[i][j], 0.f);
        const bf16* ag = g_hbuf_bf[t & 1] + (size_t)(b0 + srowA) * HH + scA;
        bf16* asd = Af + srowA * LDAB + scA;
        // stage A chunks 0-3, then 4-7 (two commit groups)
        #pragma unroll
        for (int ch = 0; ch < 4; ch++)
            #pragma unroll
            for (int q = 0; q < 32; q += 8)
                cp16(asd + ch * ACH + q, ag + ch * BKB + q);
        asm volatile("cp.async.commit_group;");
        #pragma unroll
        for (int ch = 4; ch < 8; ch++)
            #pragma unroll
            for (int q = 0; q < 32; q += 8)
                cp16(asd + ch * ACH + q, ag + ch * BKB + q);
        asm volatile("cp.async.commit_group;");

        asm volatile("cp.async.wait_group 1;" ::: "memory");
        __syncthreads();
        // burst chunks 0-3
        #pragma unroll
        for (int ch = 0; ch < 4; ch++) {
            bf16* Ab = Af + ch * ACH;
            bf16* Bb = Br + ch * BCH;
            #pragma unroll
            for (int kk = 0; kk < BKB; kk += 16) {
                FragA a0, a1; FragB bf0, bf1;
                wmma::load_matrix_sync(a0, &Ab[(wm * 32)      * LDAB + kk], LDAB);
                wmma::load_matrix_sync(a1, &Ab[(wm * 32 + 16) * LDAB + kk], LDAB);
                wmma::load_matrix_sync(bf0, &Bb[(wn * 32)      * LDAB + kk], LDAB);
                wmma::load_matrix_sync(bf1, &Bb[(wn * 32 + 16) * LDAB + kk], LDAB);
                wmma::mma_sync(c[0][0], a0, bf0, c[0][0]);
                wmma::mma_sync(c[0][1], a0, bf1, c[0][1]);
                wmma::mma_sync(c[1][0], a1, bf0, c[1][0]);
                wmma::mma_sync(c[1][1], a1, bf1, c[1][1]);
            }
        }
        asm volatile("cp.async.wait_group 0;" ::: "memory");
        __syncthreads();
        // burst chunks 4-7
        #pragma unroll
        for (int ch = 4; ch < 8; ch++) {
            bf16* Ab = Af + ch * ACH;
            bf16* Bb = Br + ch * BCH;
            #pragma unroll
            for (int kk = 0; kk < BKB; kk += 16) {
                FragA a0, a1; FragB bf0, bf1;
                wmma::load_matrix_sync(a0, &Ab[(wm * 32)      * LDAB + kk], LDAB);
                wmma::load_matrix_sync(a1, &Ab[(wm * 32 + 16) * LDAB + kk], LDAB);
                wmma::load_matrix_sync(bf0, &Bb[(wn * 32)      * LDAB + kk], LDAB);
                wmma::load_matrix_sync(bf1, &Bb[(wn * 32 + 16) * LDAB + kk], LDAB);
                wmma::mma_sync(c[0][0], a0, bf0, c[0][0]);
                wmma::mma_sync(c[0][1], a0, bf1, c[0][1]);
                wmma::mma_sync(c[1][0], a1, bf0, c[1][0]);
                wmma::mma_sync(c[1][1], a1, bf1, c[1][1]);
            }
        }
        __syncthreads();   // all warps done with Af before Cs overwrite
        #pragma unroll
        for (int i = 0; i < 2; i++)
            #pragma unroll
            for (int j = 0; j < 2; j++)
                wmma::store_matrix_sync(&Cs[(wm * 32 + i * 16) * LDC2 + wn * 32 + j * 16],
                                        c[i][j], LDC2, wmma::mem_row_major);
        __syncthreads();
        // LSTM elementwise: 128 b x 16 h
        #pragma unroll
        for (int it = 0; it < 8; it++) {
            int p = it * 256 + tid;        // 0..2047
            int row = p >> 4;
            int hh = p & 15;
            int b = b0 + row;
            if (b >= cnt) continue;
            size_t xpb = (size_t)(t * BB + b) * G4 + h0 + hh;
            float iv = Cs[row * LDC2 + 0  + hh] + g_xp[xpb];
            float fv = Cs[row * LDC2 + 16 + hh] + g_xp[xpb + 512];
            float gv = Cs[row * LDC2 + 32 + hh] + g_xp[xpb + 1024];
            float ov = Cs[row * LDC2 + 48 + hh] + g_xp[xpb + 1536];
            iv = 1.f / (1.f + __expf(-iv));
            fv = 1.f / (1.f + __expf(-fv));
            ov = 1.f / (1.f + __expf(-ov));
            gv = tanhf(gv);
            int hidx = b * HH + h0 + hh;
            float cn = fv * g_cc[hidx] + iv * gv;
            float hn = ov * tanhf(cn);
            g_cc[hidx] = cn;
            bf16 hb = __float2bfloat16(hn);
            g_hbuf_bf[(t + 1) & 1][hidx] = hb;
            g_hall_bf[(size_t)(t * BB + b) * HH + h0 + hh] = hb;
        }
        __syncthreads();   // Cs reads done before next step's A staging
        // group-local barrier (32 blocks)
        __threadfence();
        if (tid == 0) {
            int v = atomicAdd(&g_barcnt2[grp], 1);
            if (v == GRPBLK - 1) {
                atomicExch(&g_barcnt2[grp], 0);
                __threadfence();
                atomicExch(&g_barflag2[grp], t + 1);
            } else {
                volatile int* f = &g_barflag2[grp];
                while (*f < t + 1) {}
                __threadfence();
            }
        }
        __syncthreads();
    }
}

// ---- packed vocab projection: logits -> out + rowsum of exp ----
__global__ __launch_bounds__(256, 2) void k_out1(const float* __restrict__ bout,
                                                 float* __restrict__ out) {
    extern __shared__ bf16 dsm[];
    int tid = threadIdx.x;
    int m0 = blockIdx.y * 128;
    int ntot = g_ntot;
    if (m0 >= ntot) return;
    int n0 = blockIdx.x * 128;
    int srow = tid >> 1;
    int wp = tid >> 5, wm = wp & 3, wn = wp >> 2;
    int tb = g_rowmap[m0 + srow];
    const bf16* arow = g_hall_bf + (size_t)tb * HH;
    int nb = n0 + srow;
    const bf16* brow = g_Wout_bf + (size_t)(nb < VV ? nb : VV - 1) * HH;
    FragC c[2][4];
    FRAG_INIT(c);
    gemm_bf16(arow, brow, dsm, dsm + NSTG * BUFB, c, tid);
    float* Cs = (float*)dsm;
    FRAG_TO_CS(c, Cs, wm, wn);
    __syncthreads();

    int row = tid >> 1, cb = (tid & 1) * 64;
    int r = m0 + row;
    if (r < ntot) {
        int tb2 = g_rowmap[r];
        int t = tb2 >> 8, b = tb2 & 255;
        size_t obase = ((size_t)b * ML + t) * VV;
        float psum = 0.f;
        #pragma unroll
        for (int q = 0; q < 16; q++) {
            int n = n0 + cb + q * 4;
            if (n < VV) {
                float4 cv = *(const float4*)&Cs[row * LDC + cb + q * 4];
                float4 bo = *(const float4*)(bout + n);
                float4 v;
                v.x = cv.x + bo.x; v.y = cv.y + bo.y;
                v.z = cv.z + bo.z; v.w = cv.w + bo.w;
                *(float4*)(out + obase + n) = v;
                psum += __expf(v.x) + __expf(v.y) + __expf(v.z) + __expf(v.w);
            }
        }
        atomicAdd(&g_rowsum[tb2], psum);
    }
}

// ---- final: full-output pass; zeros inactive/pad, log-softmax for active ----
__global__ __launch_bounds__(256) void k_out2(float* __restrict__ out) {
    long long idx = (long long)blockIdx.x * 256 + threadIdx.x;
    const int perRow = VV / 4;
    const long long TOT = (long long)BB * ML * perRow;
    if (idx >= TOT) return;
    int r = (int)(idx / perRow);               // r = b*31 + t
    int v4 = (int)(idx % perRow);
    int b = r / ML, t = r - b * ML;
    size_t p = (size_t)r * VV + v4 * 4;
    bool active = (t < TT) && (b < g_cnt[t]);
    float4 o = make_float4(0.f, 0.f, 0.f, 0.f);
    if (active) {
        float ls = logf(g_rowsum[t * BB + b]);
        float4 lv = *(const float4*)(out + p);
        o.x = lv.x - ls; o.y = lv.y - ls; o.z = lv.z - ls; o.w = lv.w - ls;
    }
    *(float4*)(out + p) = o;
}

// ---------------- launch ----------------
extern "C" void kernel_launch(void* const* d_in, const int* in_sizes, int n_in,
                              void* d_out, int out_size) {
    const float* gimg = (const float*)d_in[0];
    const int*   w    = (const int*)d_in[1];
    const int*   cap  = (const int*)d_in[2];
    const float* emb  = (const float*)d_in[3];
    const float* Wih  = (const float*)d_in[4];
    const float* Whh  = (const float*)d_in[5];
    const float* bih  = (const float*)d_in[6];
    const float* bhh  = (const float*)d_in[7];
    const float* Wout = (const float*)d_in[8];
    const float* bout = (const float*)d_in[9];
    float* out = (float*)d_out;

    static int attr_done = 0;
    if (!attr_done) {
        cudaFuncSetAttribute(k_gproj, cudaFuncAttributeMaxDynamicSharedMemorySize, DSMEM_BYTES);
        cudaFuncSetAttribute(k_xproj, cudaFuncAttributeMaxDynamicSharedMemorySize, DSMEM_BYTES);
        cudaFuncSetAttribute(k_steps, cudaFuncAttributeMaxDynamicSharedMemorySize, DSMEM_STEPS);
        cudaFuncSetAttribute(k_out1,  cudaFuncAttributeMaxDynamicSharedMemorySize, DSMEM_BYTES);
        attr_done = 1;
    }

    k_cvt<<<(int)((N_CVT2 + 255) / 256), 256>>>(Wih, Whh, Wout, emb, gimg);
    k_prep<<<1, 256>>>(w, cap, out, (long long)out_size);
    k_init<<<512, 256>>>();
    k_gproj<<<dim3(16, 2), 256, DSMEM_BYTES>>>();
    k_xproj<<<dim3(16, 60), 256, DSMEM_BYTES>>>(w, bih, bhh);
    k_steps<<<dim3(32, 2), 256, DSMEM_STEPS>>>();
    k_out1<<<dim3(79, 60), 256, DSMEM_BYTES>>>(bout, out);
    long long tot = (long long)BB * ML * (VV / 4);
    k_out2<<<(int)((tot + 255) / 256), 256>>>(out);
}

// round 12
// speedup vs baseline: 1.0833x; 1.0256x over previous
#include <cuda_runtime.h>
#include <cuda_bf16.h>
#include <mma.h>
#include <math.h>
#include <stdint.h>

using namespace nvcuda;

// Problem constants
#define BB 256
#define TT 30
#define ML 31
#define VV 10000
#define HH 512
#define G4 2048            // 4*H
#define NROWS 7680         // TT*BB
#define BKB 64             // K-chunk (bf16 elems)
#define LDAB 72            // shared lda in bf16 elems (64 + 8 pad) -> 144B rows
#define LDC 132            // shared C ld (floats, 128 + 4 pad)
#define LDC2 68            // shared C ld for 64-wide tiles
#define BUFB (128 * LDAB)  // bf16 elems per A stage buffer (9216)
#define NSTG 3             // pipeline stages (big GEMMs)
#define DSMEM_BYTES (NSTG * 2 * BUFB * 2)          // 110592 B (128x128 GEMMs)
// k_steps: A image 8 chunks x 128 x LDAB + resident B 8 chunks x 64 x LDAB
#define ACH (128 * LDAB)   // 9216
#define BCH (64 * LDAB)    // 4608
#define NCHUNK 8
#define DSMEM_STEPS ((NCHUNK * ACH + NCHUNK * BCH) * 2)   // 221184 B
#define GRPBLK 32          // blocks per barrier group in k_steps

typedef __nv_bfloat16 bf16;

// ---------------- device scratch ----------------
__device__ int   g_order[BB];
__device__ int   g_declen[BB];
__device__ int   g_cnt[TT];
__device__ int   g_rowmap[NROWS];   // packed active row -> t*256+b
__device__ int   g_ntot;            // number of active rows
__device__ float g_gp[BB * G4];     // gimg proj + bih + bhh
__device__ float g_xp[(size_t)NROWS * G4];       // emb-proj only (raw)
__device__ float g_cc[BB * HH];
__device__ float g_rowsum[NROWS];
__device__ int   g_barcnt2[2];
__device__ int   g_barflag2[2];
// bf16 operand copies
__device__ bf16  g_Wih_bf[G4 * 1024];
__device__ bf16  g_Whh_bf[G4 * HH];
__device__ bf16  g_Wout_bf[VV * HH];
__device__ bf16  g_emb_bf[VV * HH];
__device__ bf16  g_gimg_bf[BB * HH];
__device__ bf16  g_hbuf_bf[2][BB * HH];
__device__ bf16  g_hall_bf[(size_t)NROWS * HH];

typedef wmma::fragment<wmma::matrix_a, 16, 16, 16, bf16, wmma::row_major> FragA;
typedef wmma::fragment<wmma::matrix_b, 16, 16, 16, bf16, wmma::col_major> FragB;
typedef wmma::fragment<wmma::accumulator, 16, 16, 16, float> FragC;

__device__ __forceinline__ void cp16(void* s, const void* g) {
    unsigned d = (unsigned)__cvta_generic_to_shared(s);
    asm volatile("cp.async.cg.shared.global [%0], [%1], 16;" :: "r"(d), "l"(g));
}

// ---- 3-stage pipelined bf16 GEMM: C[128x128] += A[128x512] * B[128x512]^T ----
__device__ __forceinline__ void gemm_bf16(const bf16* arow, const bf16* brow,
                                          bf16* As, bf16* Bs,
                                          FragC (&c)[2][4], int tid) {
    int wp = tid >> 5, wm = wp & 3, wn = wp >> 2;
    int srow = tid >> 1, sc = (tid & 1) * 32;
    bf16* asd = As + srow * LDAB + sc;
    bf16* bsd = Bs + srow * LDAB + sc;
    const bf16* ag = arow + sc;
    const bf16* bg = brow + sc;
    #pragma unroll
    for (int q = 0; q < 32; q += 8) { cp16(asd + q, ag + q); cp16(bsd + q, bg + q); }
    asm volatile("cp.async.commit_group;");
    #pragma unroll
    for (int q = 0; q < 32; q += 8) {
        cp16(asd + BUFB + q, ag + BKB + q);
        cp16(bsd + BUFB + q, bg + BKB + q);
    }
    asm volatile("cp.async.commit_group;");
    int buf = 0;
    #pragma unroll 1
    for (int k0 = 0; k0 < HH; k0 += BKB) {
        if (k0 + BKB < HH) asm volatile("cp.async.wait_group 1;" ::: "memory");
        else               asm volatile("cp.async.wait_group 0;" ::: "memory");
        __syncthreads();
        if (k0 + 2 * BKB < HH) {
            int nb = buf + 2; if (nb >= NSTG) nb -= NSTG;
            #pragma unroll
            for (int q = 0; q < 32; q += 8) {
                cp16(asd + nb * BUFB + q, ag + k0 + 2 * BKB + q);
                cp16(bsd + nb * BUFB + q, bg + k0 + 2 * BKB + q);
            }
            asm volatile("cp.async.commit_group;");
        }
        bf16* Ab = As + buf * BUFB;
        bf16* Bb = Bs + buf * BUFB;
        #pragma unroll
        for (int kk = 0; kk < BKB; kk += 16) {
            FragA a0, a1; FragB bf[4];
            wmma::load_matrix_sync(a0, &Ab[(wm * 32)      * LDAB + kk], LDAB);
            wmma::load_matrix_sync(a1, &Ab[(wm * 32 + 16) * LDAB + kk], LDAB);
            #pragma unroll
            for (int j = 0; j < 4; j++)
                wmma::load_matrix_sync(bf[j], &Bb[(wn * 64 + j * 16) * LDAB + kk], LDAB);
            #pragma unroll
            for (int j = 0; j < 4; j++) {
                wmma::mma_sync(c[0][j], a0, bf[j], c[0][j]);
                wmma::mma_sync(c[1][j], a1, bf[j], c[1][j]);
            }
        }
        buf = (buf == NSTG - 1) ? 0 : buf + 1;
    }
    __syncthreads();
}

#define FRAG_INIT(c)                                     \
    _Pragma("unroll")                                    \
    for (int i = 0; i < 2; i++)                          \
        _Pragma("unroll")                                \
        for (int j = 0; j < 4; j++) wmma::fill_fragment(c[i][j], 0.f);

#define FRAG_TO_CS(c, Cs, wm, wn)                                                  \
    _Pragma("unroll")                                                              \
    for (int i = 0; i < 2; i++)                                                    \
        _Pragma("unroll")                                                          \
        for (int j = 0; j < 4; j++)                                                \
            wmma::store_matrix_sync(&Cs[(wm * 32 + i * 16) * LDC + wn * 64 + j * 16], \
                                    c[i][j], LDC, wmma::mem_row_major);

// ---------------- fp32 -> bf16 conversion + state init (merged) ----------------
#define N_WIH (G4 * 1024)
#define N_WHH (G4 * HH)
#define N_WOUT (VV * HH)
#define N_EMB (VV * HH)
#define N_GIMG (BB * HH)
#define N_CVT2 ((N_WIH + N_WHH + N_WOUT + N_EMB + N_GIMG) / 2)

__global__ __launch_bounds__(256) void k_cvt(const float* __restrict__ Wih,
                                             const float* __restrict__ Whh,
                                             const float* __restrict__ Wout,
                                             const float* __restrict__ emb,
                                             const float* __restrict__ gimg) {
    long long i2 = (long long)blockIdx.x * 256 + threadIdx.x;
    // merged init work
    if (i2 < BB * HH) {
        g_hbuf_bf[0][i2] = __float2bfloat16(0.f);
        g_hbuf_bf[1][i2] = __float2bfloat16(0.f);
        g_cc[i2] = 0.f;
    }
    if (i2 < NROWS) g_rowsum[i2] = 0.f;
    if (i2 < 2) { g_barcnt2[i2] = 0; g_barflag2[i2] = 0; }
    if (i2 >= N_CVT2) return;
    long long i = i2 * 2;
    const float* src; bf16* dst; long long off;
    if (i < N_WIH)                       { src = Wih;  dst = g_Wih_bf;  off = i; }
    else if (i < (long long)N_WIH + N_WHH) { src = Whh;  dst = g_Whh_bf;  off = i - N_WIH; }
    else if (i < (long long)N_WIH + N_WHH + N_WOUT)
                                         { src = Wout; dst = g_Wout_bf; off = i - N_WIH - N_WHH; }
    else if (i < (long long)N_WIH + N_WHH + N_WOUT + N_EMB)
                                         { src = emb;  dst = g_emb_bf;  off = i - N_WIH - N_WHH - N_WOUT; }
    else                                 { src = gimg; dst = g_gimg_bf; off = i - N_WIH - N_WHH - N_WOUT - N_EMB; }
    float2 v = *(const float2*)(src + off);
    __nv_bfloat162 o = __floats2bfloat162_rn(v.x, v.y);
    *(__nv_bfloat162*)(dst + off) = o;
}

// ---------------- prep: sort + targets + packed row map ----------------
__global__ void k_prep(const int* __restrict__ w, const int* __restrict__ cap,
                       float* __restrict__ out, long long out_size) {
    __shared__ int lens[BB];
    __shared__ int off[TT + 1];
    int i = threadIdx.x;
    lens[i] = cap[i];
    __syncthreads();
    int li = lens[i];
    int rank = 0;
    #pragma unroll 8
    for (int j = 0; j < BB; j++) {
        int lj = lens[j];
        rank += (lj > li) || (lj == li && j < i);
    }
    g_order[rank]  = i;
    g_declen[rank] = li - 1;
    __syncthreads();

    if (i < TT) {
        int c = 0;
        for (int j = 0; j < BB; j++) c += (g_declen[j] > i);
        g_cnt[i] = c;
    }
    __syncthreads();
    if (i == 0) {
        int s = 0;
        for (int t = 0; t < TT; t++) { off[t] = s; s += g_cnt[t]; }
        off[TT] = s;
        g_ntot = s;
    }
    __syncthreads();
    for (int t = 0; t < TT; t++) {
        int c = g_cnt[t];
        for (int b = i; b < c; b += 256) g_rowmap[off[t] + b] = t * 256 + b;
    }
    for (int r = off[TT] + i; r < NROWS; r += 256) g_rowmap[r] = 0;

    long long PRED = (long long)BB * ML * VV;
    if (out_size >= PRED + (long long)BB * TT + BB) {
        int src = g_order[i];
        for (int k = 0; k < TT; k++)
            out[PRED + (long long)i * TT + k] = (float)w[src * ML + k + 1];
        out[PRED + (long long)BB * TT + i] = (float)g_declen[i];
    }
}

// ---- union projection kernel: y<60 -> packed emb proj (raw xp),
//      y>=60 -> image proj + biases (gp). Independent, runs concurrently. ----
__global__ __launch_bounds__(256, 2) void k_proj(const int* __restrict__ w,
                                                 const float* __restrict__ bih,
                                                 const float* __restrict__ bhh) {
    extern __shared__ bf16 dsm[];
    int tid = threadIdx.x;
    int srow = tid >> 1;
    int wp = tid >> 5, wm = wp & 3, wn = wp >> 2;
    int n0 = blockIdx.x * 128;

    if (blockIdx.y >= 60) {
        // ---- gproj branch: gp[b][n] = gimg[order[b]] . Wih[n][0:512] + bih + bhh
        int m0 = (blockIdx.y - 60) * 128;
        const bf16* arow = g_gimg_bf + (size_t)g_order[m0 + srow] * HH;
        const bf16* brow = g_Wih_bf + (size_t)(n0 + srow) * 1024;
        FragC c[2][4];
        FRAG_INIT(c);
        gemm_bf16(arow, brow, dsm, dsm + NSTG * BUFB, c, tid);
        float* Cs = (float*)dsm;
        FRAG_TO_CS(c, Cs, wm, wn);
        __syncthreads();
        int row = tid >> 1, cb = (tid & 1) * 64;
        int b = m0 + row;
        #pragma unroll
        for (int q = 0; q < 16; q++) {
            int n = n0 + cb + q * 4;
            float4 cv = *(const float4*)&Cs[row * LDC + cb + q * 4];
            float4 b1 = *(const float4*)(bih + n);
            float4 b2 = *(const float4*)(bhh + n);
            float4 v;
            v.x = cv.x + b1.x + b2.x;
            v.y = cv.y + b1.y + b2.y;
            v.z = cv.z + b1.z + b2.z;
            v.w = cv.w + b1.w + b2.w;
            *(float4*)(g_gp + (size_t)b * G4 + n) = v;
        }
        return;
    }

    // ---- xproj branch: raw xp[r][n] = emb[word(r)] . Wih[n][512:1024]
    int m0 = blockIdx.y * 128;
    int ntot = g_ntot;
    if (m0 >= ntot) return;
    int tb = g_rowmap[m0 + srow];
    int t_r = tb >> 8, b_r = tb & 255;
    int word = w[g_order[b_r] * ML + t_r];
    const bf16* arow = g_emb_bf + (size_t)word * HH;
    const bf16* brow = g_Wih_bf + (size_t)(n0 + srow) * 1024 + 512;
    FragC c[2][4];
    FRAG_INIT(c);
    gemm_bf16(arow, brow, dsm, dsm + NSTG * BUFB, c, tid);
    float* Cs = (float*)dsm;
    FRAG_TO_CS(c, Cs, wm, wn);
    __syncthreads();
    int row = tid >> 1, cb = (tid & 1) * 64;
    int r = m0 + row;
    if (r < ntot) {
        int tb2 = g_rowmap[r];
        size_t xb = (size_t)tb2 * G4;
        #pragma unroll
        for (int q = 0; q < 16; q++) {
            int n = n0 + cb + q * 4;
            *(float4*)(g_xp + xb + n) = *(const float4*)&Cs[row * LDC + cb + q * 4];
        }
    }
}

// ---- persistent recurrent kernel (R9 design; epilogue adds gp + xp) ----
__global__ __launch_bounds__(256) void k_steps() {
    extern __shared__ bf16 dsm[];
    bf16* Af = dsm;
    bf16* Br = dsm + NCHUNK * ACH;
    float* Cs = (float*)dsm;
    int tid = threadIdx.x;
    int h0 = blockIdx.x * 16;
    int grp = blockIdx.y;
    int b0 = grp * 128;
    int wp = tid >> 5, wm = wp & 3, wn = wp >> 2;
    int srowA = tid >> 1, scA = (tid & 1) * 32;

    {
        int row = tid >> 2, c16 = (tid & 3) * 16;
        int gate = row >> 4, hh_s = row & 15;
        const bf16* bg = g_Whh_bf + (size_t)(gate * 512 + h0 + hh_s) * HH;
        #pragma unroll
        for (int ch = 0; ch < NCHUNK; ch++) {
            bf16* d = Br + ch * BCH + row * LDAB + c16;
            const bf16* s = bg + ch * BKB + c16;
            cp16(d, s); cp16(d + 8, s + 8);
        }
        asm volatile("cp.async.commit_group;");
        asm volatile("cp.async.wait_group 0;" ::: "memory");
        __syncthreads();
    }

    for (int t = 0; t < TT; t++) {
        int cnt = g_cnt[t];
        if (cnt <= b0) break;
        FragC c[2][2];
        #pragma unroll
        for (int i = 0; i < 2; i++)
            #pragma unroll
            for (int j = 0; j < 2; j++) wmma::fill_fragment(c[i][j], 0.f);
        const bf16* ag = g_hbuf_bf[t & 1] + (size_t)(b0 + srowA) * HH + scA;
        bf16* asd = Af + srowA * LDAB + scA;
        #pragma unroll
        for (int ch = 0; ch < 4; ch++)
            #pragma unroll
            for (int q = 0; q < 32; q += 8)
                cp16(asd + ch * ACH + q, ag + ch * BKB + q);
        asm volatile("cp.async.commit_group;");
        #pragma unroll
        for (int ch = 4; ch < 8; ch++)
            #pragma unroll
            for (int q = 0; q < 32; q += 8)
                cp16(asd + ch * ACH + q, ag + ch * BKB + q);
        asm volatile("cp.async.commit_group;");

        asm volatile("cp.async.wait_group 1;" ::: "memory");
        __syncthreads();
        #pragma unroll
        for (int ch = 0; ch < 4; ch++) {
            bf16* Ab = Af + ch * ACH;
            bf16* Bb = Br + ch * BCH;
            #pragma unroll
            for (int kk = 0; kk < BKB; kk += 16) {
                FragA a0, a1; FragB bf0, bf1;
                wmma::load_matrix_sync(a0, &Ab[(wm * 32)      * LDAB + kk], LDAB);
                wmma::load_matrix_sync(a1, &Ab[(wm * 32 + 16) * LDAB + kk], LDAB);
                wmma::load_matrix_sync(bf0, &Bb[(wn * 32)      * LDAB + kk], LDAB);
                wmma::load_matrix_sync(bf1, &Bb[(wn * 32 + 16) * LDAB + kk], LDAB);
                wmma::mma_sync(c[0][0], a0, bf0, c[0][0]);
                wmma::mma_sync(c[0][1], a0, bf1, c[0][1]);
                wmma::mma_sync(c[1][0], a1, bf0, c[1][0]);
                wmma::mma_sync(c[1][1], a1, bf1, c[1][1]);
            }
        }
        asm volatile("cp.async.wait_group 0;" ::: "memory");
        __syncthreads();
        #pragma unroll
        for (int ch = 4; ch < 8; ch++) {
            bf16* Ab = Af + ch * ACH;
            bf16* Bb = Br + ch * BCH;
            #pragma unroll
            for (int kk = 0; kk < BKB; kk += 16) {
                FragA a0, a1; FragB bf0, bf1;
                wmma::load_matrix_sync(a0, &Ab[(wm * 32)      * LDAB + kk], LDAB);
                wmma::load_matrix_sync(a1, &Ab[(wm * 32 + 16) * LDAB + kk], LDAB);
                wmma::load_matrix_sync(bf0, &Bb[(wn * 32)      * LDAB + kk], LDAB);
                wmma::load_matrix_sync(bf1, &Bb[(wn * 32 + 16) * LDAB + kk], LDAB);
                wmma::mma_sync(c[0][0], a0, bf0, c[0][0]);
                wmma::mma_sync(c[0][1], a0, bf1, c[0][1]);
                wmma::mma_sync(c[1][0], a1, bf0, c[1][0]);
                wmma::mma_sync(c[1][1], a1, bf1, c[1][1]);
            }
        }
        __syncthreads();
        #pragma unroll
        for (int i = 0; i < 2; i++)
            #pragma unroll
            for (int j = 0; j < 2; j++)
                wmma::store_matrix_sync(&Cs[(wm * 32 + i * 16) * LDC2 + wn * 32 + j * 16],
                                        c[i][j], LDC2, wmma::mem_row_major);
        __syncthreads();
        #pragma unroll
        for (int it = 0; it < 8; it++) {
            int p = it * 256 + tid;
            int row = p >> 4;
            int hh = p & 15;
            int b = b0 + row;
            if (b >= cnt) continue;
            size_t xpb = (size_t)(t * BB + b) * G4 + h0 + hh;
            size_t gpb = (size_t)b * G4 + h0 + hh;
            float iv = Cs[row * LDC2 + 0  + hh] + g_xp[xpb]        + g_gp[gpb];
            float fv = Cs[row * LDC2 + 16 + hh] + g_xp[xpb + 512]  + g_gp[gpb + 512];
            float gv = Cs[row * LDC2 + 32 + hh] + g_xp[xpb + 1024] + g_gp[gpb + 1024];
            float ov = Cs[row * LDC2 + 48 + hh] + g_xp[xpb + 1536] + g_gp[gpb + 1536];
            iv = 1.f / (1.f + __expf(-iv));
            fv = 1.f / (1.f + __expf(-fv));
            ov = 1.f / (1.f + __expf(-ov));
            gv = tanhf(gv);
            int hidx = b * HH + h0 + hh;
            float cn = fv * g_cc[hidx] + iv * gv;
            float hn = ov * tanhf(cn);
            g_cc[hidx] = cn;
            bf16 hb = __float2bfloat16(hn);
            g_hbuf_bf[(t + 1) & 1][hidx] = hb;
            g_hall_bf[(size_t)(t * BB + b) * HH + h0 + hh] = hb;
        }
        __syncthreads();
        __threadfence();
        if (tid == 0) {
            int v = atomicAdd(&g_barcnt2[grp], 1);
            if (v == GRPBLK - 1) {
                atomicExch(&g_barcnt2[grp], 0);
                __threadfence();
                atomicExch(&g_barflag2[grp], t + 1);
            } else {
                while (atomicAdd(&g_barflag2[grp], 0) < t + 1) { __nanosleep(32); }
                __threadfence();
            }
        }
        __syncthreads();
    }
}

// ---- packed vocab projection (wmma): logits -> out + rowsum of exp ----
__global__ __launch_bounds__(256, 2) void k_out1(const float* __restrict__ bout,
                                                 float* __restrict__ out) {
    extern __shared__ bf16 dsm[];
    int tid = threadIdx.x;
    int m0 = blockIdx.y * 128;
    int ntot = g_ntot;
    if (m0 >= ntot) return;
    int n0 = blockIdx.x * 128;
    int srow = tid >> 1;
    int wp = tid >> 5, wm = wp & 3, wn = wp >> 2;
    int tb = g_rowmap[m0 + srow];
    const bf16* arow = g_hall_bf + (size_t)tb * HH;
    int nb = n0 + srow;
    const bf16* brow = g_Wout_bf + (size_t)(nb < VV ? nb : VV - 1) * HH;
    FragC c[2][4];
    FRAG_INIT(c);
    gemm_bf16(arow, brow, dsm, dsm + NSTG * BUFB, c, tid);
    float* Cs = (float*)dsm;
    FRAG_TO_CS(c, Cs, wm, wn);
    __syncthreads();

    int row = tid >> 1, cb = (tid & 1) * 64;
    int r = m0 + row;
    if (r < ntot) {
        int tb2 = g_rowmap[r];
        int t = tb2 >> 8, b = tb2 & 255;
        size_t obase = ((size_t)b * ML + t) * VV;
        float psum = 0.f;
        #pragma unroll
        for (int q = 0; q < 16; q++) {
            int n = n0 + cb + q * 4;
            if (n < VV) {
                float4 cv = *(const float4*)&Cs[row * LDC + cb + q * 4];
                float4 bo = *(const float4*)(bout + n);
                float4 v;
                v.x = cv.x + bo.x; v.y = cv.y + bo.y;
                v.z = cv.z + bo.z; v.w = cv.w + bo.w;
                *(float4*)(out + obase + n) = v;
                psum += __expf(v.x) + __expf(v.y) + __expf(v.z) + __expf(v.w);
            }
        }
        atomicAdd(&g_rowsum[tb2], psum);
    }
}

// ---- final: full-output pass; zeros inactive/pad, log-softmax for active ----
__global__ __launch_bounds__(256) void k_out2(float* __restrict__ out) {
    long long idx = (long long)blockIdx.x * 256 + threadIdx.x;
    const int perRow = VV / 4;
    const long long TOT = (long long)BB * ML * perRow;
    if (idx >= TOT) return;
    int r = (int)(idx / perRow);
    int v4 = (int)(idx % perRow);
    int b = r / ML, t = r - b * ML;
    size_t p = (size_t)r * VV + v4 * 4;
    bool active = (t < TT) && (b < g_cnt[t]);
    float4 o = make_float4(0.f, 0.f, 0.f, 0.f);
    if (active) {
        float ls = logf(g_rowsum[t * BB + b]);
        float4 lv = *(const float4*)(out + p);
        o.x = lv.x - ls; o.y = lv.y - ls; o.z = lv.z - ls; o.w = lv.w - ls;
    }
    *(float4*)(out + p) = o;
}

// ---------------- launch ----------------
extern "C" void kernel_launch(void* const* d_in, const int* in_sizes, int n_in,
                              void* d_out, int out_size) {
    const float* gimg = (const float*)d_in[0];
    const int*   w    = (const int*)d_in[1];
    const int*   cap  = (const int*)d_in[2];
    const float* emb  = (const float*)d_in[3];
    const float* Wih  = (const float*)d_in[4];
    const float* Whh  = (const float*)d_in[5];
    const float* bih  = (const float*)d_in[6];
    const float* bhh  = (const float*)d_in[7];
    const float* Wout = (const float*)d_in[8];
    const float* bout = (const float*)d_in[9];
    float* out = (float*)d_out;

    static int attr_done = 0;
    if (!attr_done) {
        cudaFuncSetAttribute(k_proj,  cudaFuncAttributeMaxDynamicSharedMemorySize, DSMEM_BYTES);
        cudaFuncSetAttribute(k_steps, cudaFuncAttributeMaxDynamicSharedMemorySize, DSMEM_STEPS);
        cudaFuncSetAttribute(k_out1,  cudaFuncAttributeMaxDynamicSharedMemorySize, DSMEM_BYTES);
        attr_done = 1;
    }

    k_cvt<<<(int)((N_CVT2 + 255) / 256), 256>>>(Wih, Whh, Wout, emb, gimg);
    k_prep<<<1, 256>>>(w, cap, out, (long long)out_size);
    k_proj<<<dim3(16, 62), 256, DSMEM_BYTES>>>(w, bih, bhh);
    k_steps<<<dim3(32, 2), 256, DSMEM_STEPS>>>();
    k_out1<<<dim3(79, 60), 256, DSMEM_BYTES>>>(bout, out);
    long long tot = (long long)BB * ML * (VV / 4);
    k_out2<<<(int)((tot + 255) / 256), 256>>>(out);
}

// round 13
// speedup vs baseline: 1.1273x; 1.0406x over previous
#include <cuda_runtime.h>
#include <cuda_bf16.h>
#include <mma.h>
#include <math.h>
#include <stdint.h>

using namespace nvcuda;

// Problem constants
#define BB 256
#define TT 30
#define ML 31
#define VV 10000
#define HH 512
#define G4 2048            // 4*H
#define NROWS 7680         // TT*BB
#define BKB 64             // K-chunk (bf16 elems)
#define LDAB 72            // shared lda in bf16 elems (64 + 8 pad) -> 144B rows
#define LDC 132            // shared C ld (floats, 128 + 4 pad)
#define LDC2 68            // shared C ld for 64-wide tiles
#define BUFB (128 * LDAB)  // bf16 elems per A stage buffer (9216)
#define NSTG 3             // pipeline stages (big GEMMs)
#define DSMEM_BYTES (NSTG * 2 * BUFB * 2)          // 110592 B (128x128 GEMMs)
// k_steps: 3-stage A (3 x ACH) + resident B (8 x BCH) + gp/xp/cc float tiles
#define ACH (128 * LDAB)   // 9216 bf16
#define BCH (64 * LDAB)    // 4608 bf16
#define NCHUNK 8
#define FS_GP 0            // float offsets within float region
#define FS_XP 8192
#define FS_CC 16384
#define DSMEM_STEPS ((3 * ACH + NCHUNK * BCH) * 2 + (8192 + 8192 + 2048) * 4)  // 202752 B
#define GRPBLK 32          // blocks per barrier group in k_steps

typedef __nv_bfloat16 bf16;

// ---------------- device scratch ----------------
__device__ int   g_order[BB];
__device__ int   g_declen[BB];
__device__ int   g_cnt[TT];
__device__ int   g_rowmap[NROWS];   // packed active row -> t*256+b
__device__ int   g_ntot;            // number of active rows
__device__ float g_gp[BB * G4];     // gimg proj + bih + bhh
__device__ float g_xp[(size_t)NROWS * G4];       // emb-proj only (raw)
__device__ float g_rowsum[NROWS];
__device__ int   g_barcnt2[2];
__device__ int   g_barflag2[2];
// bf16 operand copies
__device__ bf16  g_Wih_bf[G4 * 1024];
__device__ bf16  g_Whh_bf[G4 * HH];
__device__ bf16  g_Wout_bf[VV * HH];
__device__ bf16  g_emb_bf[VV * HH];
__device__ bf16  g_gimg_bf[BB * HH];
__device__ bf16  g_hbuf_bf[2][BB * HH];
__device__ bf16  g_hall_bf[(size_t)NROWS * HH];

typedef wmma::fragment<wmma::matrix_a, 16, 16, 16, bf16, wmma::row_major> FragA;
typedef wmma::fragment<wmma::matrix_b, 16, 16, 16, bf16, wmma::col_major> FragB;
typedef wmma::fragment<wmma::accumulator, 16, 16, 16, float> FragC;

__device__ __forceinline__ void cp16(void* s, const void* g) {
    unsigned d = (unsigned)__cvta_generic_to_shared(s);
    asm volatile("cp.async.cg.shared.global [%0], [%1], 16;" :: "r"(d), "l"(g));
}

// ---- 3-stage pipelined bf16 GEMM: C[128x128] += A[128x512] * B[128x512]^T ----
__device__ __forceinline__ void gemm_bf16(const bf16* arow, const bf16* brow,
                                          bf16* As, bf16* Bs,
                                          FragC (&c)[2][4], int tid) {
    int wp = tid >> 5, wm = wp & 3, wn = wp >> 2;
    int srow = tid >> 1, sc = (tid & 1) * 32;
    bf16* asd = As + srow * LDAB + sc;
    bf16* bsd = Bs + srow * LDAB + sc;
    const bf16* ag = arow + sc;
    const bf16* bg = brow + sc;
    #pragma unroll
    for (int q = 0; q < 32; q += 8) { cp16(asd + q, ag + q); cp16(bsd + q, bg + q); }
    asm volatile("cp.async.commit_group;");
    #pragma unroll
    for (int q = 0; q < 32; q += 8) {
        cp16(asd + BUFB + q, ag + BKB + q);
        cp16(bsd + BUFB + q, bg + BKB + q);
    }
    asm volatile("cp.async.commit_group;");
    int buf = 0;
    #pragma unroll 1
    for (int k0 = 0; k0 < HH; k0 += BKB) {
        if (k0 + BKB < HH) asm volatile("cp.async.wait_group 1;" ::: "memory");
        else               asm volatile("cp.async.wait_group 0;" ::: "memory");
        __syncthreads();
        if (k0 + 2 * BKB < HH) {
            int nb = buf + 2; if (nb >= NSTG) nb -= NSTG;
            #pragma unroll
            for (int q = 0; q < 32; q += 8) {
                cp16(asd + nb * BUFB + q, ag + k0 + 2 * BKB + q);
                cp16(bsd + nb * BUFB + q, bg + k0 + 2 * BKB + q);
            }
            asm volatile("cp.async.commit_group;");
        }
        bf16* Ab = As + buf * BUFB;
        bf16* Bb = Bs + buf * BUFB;
        #pragma unroll
        for (int kk = 0; kk < BKB; kk += 16) {
            FragA a0, a1; FragB bf[4];
            wmma::load_matrix_sync(a0, &Ab[(wm * 32)      * LDAB + kk], LDAB);
            wmma::load_matrix_sync(a1, &Ab[(wm * 32 + 16) * LDAB + kk], LDAB);
            #pragma unroll
            for (int j = 0; j < 4; j++)
                wmma::load_matrix_sync(bf[j], &Bb[(wn * 64 + j * 16) * LDAB + kk], LDAB);
            #pragma unroll
            for (int j = 0; j < 4; j++) {
                wmma::mma_sync(c[0][j], a0, bf[j], c[0][j]);
                wmma::mma_sync(c[1][j], a1, bf[j], c[1][j]);
            }
        }
        buf = (buf == NSTG - 1) ? 0 : buf + 1;
    }
    __syncthreads();
}

#define FRAG_INIT(c)                                     \
    _Pragma("unroll")                                    \
    for (int i = 0; i < 2; i++)                          \
        _Pragma("unroll")                                \
        for (int j = 0; j < 4; j++) wmma::fill_fragment(c[i][j], 0.f);

#define FRAG_TO_CS(c, Cs, wm, wn)                                                  \
    _Pragma("unroll")                                                              \
    for (int i = 0; i < 2; i++)                                                    \
        _Pragma("unroll")                                                          \
        for (int j = 0; j < 4; j++)                                                \
            wmma::store_matrix_sync(&Cs[(wm * 32 + i * 16) * LDC + wn * 64 + j * 16], \
                                    c[i][j], LDC, wmma::mem_row_major);

// ---------------- fp32 -> bf16 conversion + state init (merged) ----------------
#define N_WIH (G4 * 1024)
#define N_WHH (G4 * HH)
#define N_WOUT (VV * HH)
#define N_EMB (VV * HH)
#define N_GIMG (BB * HH)
#define N_CVT2 ((N_WIH + N_WHH + N_WOUT + N_EMB + N_GIMG) / 2)

__global__ __launch_bounds__(256) void k_cvt(const float* __restrict__ Wih,
                                             const float* __restrict__ Whh,
                                             const float* __restrict__ Wout,
                                             const float* __restrict__ emb,
                                             const float* __restrict__ gimg) {
    long long i2 = (long long)blockIdx.x * 256 + threadIdx.x;
    // merged init work
    if (i2 < BB * HH) {
        g_hbuf_bf[0][i2] = __float2bfloat16(0.f);
        g_hbuf_bf[1][i2] = __float2bfloat16(0.f);
    }
    if (i2 < NROWS) g_rowsum[i2] = 0.f;
    if (i2 < 2) { g_barcnt2[i2] = 0; g_barflag2[i2] = 0; }
    if (i2 >= N_CVT2) return;
    long long i = i2 * 2;
    const float* src; bf16* dst; long long off;
    if (i < N_WIH)                       { src = Wih;  dst = g_Wih_bf;  off = i; }
    else if (i < (long long)N_WIH + N_WHH) { src = Whh;  dst = g_Whh_bf;  off = i - N_WIH; }
    else if (i < (long long)N_WIH + N_WHH + N_WOUT)
                                         { src = Wout; dst = g_Wout_bf; off = i - N_WIH - N_WHH; }
    else if (i < (long long)N_WIH + N_WHH + N_WOUT + N_EMB)
                                         { src = emb;  dst = g_emb_bf;  off = i - N_WIH - N_WHH - N_WOUT; }
    else                                 { src = gimg; dst = g_gimg_bf; off = i - N_WIH - N_WHH - N_WOUT - N_EMB; }
    float2 v = *(const float2*)(src + off);
    __nv_bfloat162 o = __floats2bfloat162_rn(v.x, v.y);
    *(__nv_bfloat162*)(dst + off) = o;
}

// ---------------- prep: sort + targets + packed row map ----------------
__global__ void k_prep(const int* __restrict__ w, const int* __restrict__ cap,
                       float* __restrict__ out, long long out_size) {
    __shared__ int lens[BB];
    __shared__ int off[TT + 1];
    int i = threadIdx.x;
    lens[i] = cap[i];
    __syncthreads();
    int li = lens[i];
    int rank = 0;
    #pragma unroll 8
    for (int j = 0; j < BB; j++) {
        int lj = lens[j];
        rank += (lj > li) || (lj == li && j < i);
    }
    g_order[rank]  = i;
    g_declen[rank] = li - 1;
    __syncthreads();

    if (i < TT) {
        int c = 0;
        for (int j = 0; j < BB; j++) c += (g_declen[j] > i);
        g_cnt[i] = c;
    }
    __syncthreads();
    if (i == 0) {
        int s = 0;
        for (int t = 0; t < TT; t++) { off[t] = s; s += g_cnt[t]; }
        off[TT] = s;
        g_ntot = s;
    }
    __syncthreads();
    for (int t = 0; t < TT; t++) {
        int c = g_cnt[t];
        for (int b = i; b < c; b += 256) g_rowmap[off[t] + b] = t * 256 + b;
    }
    for (int r = off[TT] + i; r < NROWS; r += 256) g_rowmap[r] = 0;

    long long PRED = (long long)BB * ML * VV;
    if (out_size >= PRED + (long long)BB * TT + BB) {
        int src = g_order[i];
        for (int k = 0; k < TT; k++)
            out[PRED + (long long)i * TT + k] = (float)w[src * ML + k + 1];
        out[PRED + (long long)BB * TT + i] = (float)g_declen[i];
    }
}

// ---- union projection kernel: y<60 -> packed emb proj (raw xp),
//      y>=60 -> image proj + biases (gp). Independent, runs concurrently. ----
__global__ __launch_bounds__(256, 2) void k_proj(const int* __restrict__ w,
                                                 const float* __restrict__ bih,
                                                 const float* __restrict__ bhh) {
    extern __shared__ bf16 dsm[];
    int tid = threadIdx.x;
    int srow = tid >> 1;
    int wp = tid >> 5, wm = wp & 3, wn = wp >> 2;
    int n0 = blockIdx.x * 128;

    if (blockIdx.y >= 60) {
        // ---- gproj branch: gp[b][n] = gimg[order[b]] . Wih[n][0:512] + bih + bhh
        int m0 = (blockIdx.y - 60) * 128;
        const bf16* arow = g_gimg_bf + (size_t)g_order[m0 + srow] * HH;
        const bf16* brow = g_Wih_bf + (size_t)(n0 + srow) * 1024;
        FragC c[2][4];
        FRAG_INIT(c);
        gemm_bf16(arow, brow, dsm, dsm + NSTG * BUFB, c, tid);
        float* Cs = (float*)dsm;
        FRAG_TO_CS(c, Cs, wm, wn);
        __syncthreads();
        int row = tid >> 1, cb = (tid & 1) * 64;
        int b = m0 + row;
        #pragma unroll
        for (int q = 0; q < 16; q++) {
            int n = n0 + cb + q * 4;
            float4 cv = *(const float4*)&Cs[row * LDC + cb + q * 4];
            float4 b1 = *(const float4*)(bih + n);
            float4 b2 = *(const float4*)(bhh + n);
            float4 v;
            v.x = cv.x + b1.x + b2.x;
            v.y = cv.y + b1.y + b2.y;
            v.z = cv.z + b1.z + b2.z;
            v.w = cv.w + b1.w + b2.w;
            *(float4*)(g_gp + (size_t)b * G4 + n) = v;
        }
        return;
    }

    // ---- xproj branch: raw xp[r][n] = emb[word(r)] . Wih[n][512:1024]
    int m0 = blockIdx.y * 128;
    int ntot = g_ntot;
    if (m0 >= ntot) return;
    int tb = g_rowmap[m0 + srow];
    int t_r = tb >> 8, b_r = tb & 255;
    int word = w[g_order[b_r] * ML + t_r];
    const bf16* arow = g_emb_bf + (size_t)word * HH;
    const bf16* brow = g_Wih_bf + (size_t)(n0 + srow) * 1024 + 512;
    FragC c[2][4];
    FRAG_INIT(c);
    gemm_bf16(arow, brow, dsm, dsm + NSTG * BUFB, c, tid);
    float* Cs = (float*)dsm;
    FRAG_TO_CS(c, Cs, wm, wn);
    __syncthreads();
    int row = tid >> 1, cb = (tid & 1) * 64;
    int r = m0 + row;
    if (r < ntot) {
        int tb2 = g_rowmap[r];
        size_t xb = (size_t)tb2 * G4;
        #pragma unroll
        for (int q = 0; q < 16; q++) {
            int n = n0 + cb + q * 4;
            *(float4*)(g_xp + xb + n) = *(const float4*)&Cs[row * LDC + cb + q * 4];
        }
    }
}

// ---- persistent recurrent kernel v4: 3-stage A, resident B, smem cc/gp,
//      xp(t) prefetched under the mma burst. All epilogue inputs in smem. ----
__global__ __launch_bounds__(256) void k_steps() {
    extern __shared__ bf16 dsm[];
    bf16* Af = dsm;                          // 3 x ACH
    bf16* Br = dsm + 3 * ACH;                // 8 x BCH
    float* fsm = (float*)(dsm + 3 * ACH + NCHUNK * BCH);
    float* gpS = fsm + FS_GP;                // 128 x 64
    float* xpS = fsm + FS_XP;                // 128 x 64
    float* ccS = fsm + FS_CC;                // 128 x 16
    float* Cs = (float*)dsm;                 // aliases Af after bursts
    int tid = threadIdx.x;
    int h0 = blockIdx.x * 16;
    int grp = blockIdx.y;
    int b0 = grp * 128;
    int wp = tid >> 5, wm = wp & 3, wn = wp >> 2;
    int srowA = tid >> 1, scA = (tid & 1) * 32;
    int rowX = tid >> 1, halfX = tid & 1;

    // ---- one-time staging: resident B (W_hh) + gp tile; zero cc ----
    {
        int row4 = tid >> 2, c16 = (tid & 3) * 16;
        int gate = row4 >> 4, hh_s = row4 & 15;
        const bf16* bg = g_Whh_bf + (size_t)(gate * 512 + h0 + hh_s) * HH;
        #pragma unroll
        for (int ch = 0; ch < NCHUNK; ch++) {
            bf16* d = Br + ch * BCH + row4 * LDAB + c16;
            const bf16* s = bg + ch * BKB + c16;
            cp16(d, s); cp16(d + 8, s + 8);
        }
        const float* gsrc = g_gp + (size_t)(b0 + rowX) * G4 + h0;
        #pragma unroll
        for (int g2 = 0; g2 < 2; g2++) {
            int gate2 = halfX * 2 + g2;
            const float* s = gsrc + gate2 * 512;
            float* d = gpS + rowX * 64 + gate2 * 16;
            cp16(d, s); cp16(d + 4, s + 4); cp16(d + 8, s + 8); cp16(d + 12, s + 12);
        }
        asm volatile("cp.async.commit_group;");
        asm volatile("cp.async.wait_group 0;" ::: "memory");
        #pragma unroll
        for (int i = 0; i < 8; i++) ccS[tid * 8 + i] = 0.f;
        __syncthreads();
    }

    for (int t = 0; t < TT; t++) {
        int cnt = g_cnt[t];
        if (cnt <= b0) break;
        FragC c[2][2];
        #pragma unroll
        for (int i = 0; i < 2; i++)
            #pragma unroll
            for (int j = 0; j < 2; j++) wmma::fill_fragment(c[i][j], 0.f);
        const bf16* ag = g_hbuf_bf[t & 1] + (size_t)(b0 + srowA) * HH + scA;
        bf16* asd = Af + srowA * LDAB + scA;
        // prologue: chunk0 -> buf0 (G0), chunk1 -> buf1 (G1)
        #pragma unroll
        for (int q = 0; q < 32; q += 8) cp16(asd + q, ag + q);
        asm volatile("cp.async.commit_group;");
        #pragma unroll
        for (int q = 0; q < 32; q += 8) cp16(asd + ACH + q, ag + BKB + q);
        asm volatile("cp.async.commit_group;");

        #pragma unroll 1
        for (int ch = 0; ch < NCHUNK; ch++) {
            if (ch < NCHUNK - 1) asm volatile("cp.async.wait_group 1;" ::: "memory");
            else                 asm volatile("cp.async.wait_group 0;" ::: "memory");
            __syncthreads();
            if (ch < NCHUNK - 2) {
                int dch = ch + 2;
                int dbuf = dch; while (dbuf >= 3) dbuf -= 3;
                #pragma unroll
                for (int q = 0; q < 32; q += 8)
                    cp16(asd + dbuf * ACH + q, ag + dch * BKB + q);
                if (ch == 0) {
                    // xp(t) prefetch rides G2; retired by chunk-2's wait
                    const float* xsrc = g_xp + (size_t)(t * BB + b0 + rowX) * G4 + h0;
                    #pragma unroll
                    for (int g2 = 0; g2 < 2; g2++) {
                        int gate2 = halfX * 2 + g2;
                        const float* s = xsrc + gate2 * 512;
                        float* d = xpS + rowX * 64 + gate2 * 16;
                        cp16(d, s); cp16(d + 4, s + 4);
                        cp16(d + 8, s + 8); cp16(d + 12, s + 12);
                    }
                }
                asm volatile("cp.async.commit_group;");
            }
            int cbuf = ch; while (cbuf >= 3) cbuf -= 3;
            bf16* Ab = Af + cbuf * ACH;
            bf16* Bb = Br + ch * BCH;
            #pragma unroll
            for (int kk = 0; kk < BKB; kk += 16) {
                FragA a0, a1; FragB bf0, bf1;
                wmma::load_matrix_sync(a0, &Ab[(wm * 32)      * LDAB + kk], LDAB);
                wmma::load_matrix_sync(a1, &Ab[(wm * 32 + 16) * LDAB + kk], LDAB);
                wmma::load_matrix_sync(bf0, &Bb[(wn * 32)      * LDAB + kk], LDAB);
                wmma::load_matrix_sync(bf1, &Bb[(wn * 32 + 16) * LDAB + kk], LDAB);
                wmma::mma_sync(c[0][0], a0, bf0, c[0][0]);
                wmma::mma_sync(c[0][1], a0, bf1, c[0][1]);
                wmma::mma_sync(c[1][0], a1, bf0, c[1][0]);
                wmma::mma_sync(c[1][1], a1, bf1, c[1][1]);
            }
        }
        __syncthreads();   // all warps done reading Af before Cs overwrite
        #pragma unroll
        for (int i = 0; i < 2; i++)
            #pragma unroll
            for (int j = 0; j < 2; j++)
                wmma::store_matrix_sync(&Cs[(wm * 32 + i * 16) * LDC2 + wn * 32 + j * 16],
                                        c[i][j], LDC2, wmma::mem_row_major);
        __syncthreads();
        // LSTM elementwise: all inputs in smem
        #pragma unroll
        for (int it = 0; it < 8; it++) {
            int p = it * 256 + tid;
            int row = p >> 4;
            int hh = p & 15;
            int b = b0 + row;
            if (b >= cnt) continue;
            int r64 = row * 64 + hh;
            float iv = Cs[row * LDC2 + 0  + hh] + xpS[r64]      + gpS[r64];
            float fv = Cs[row * LDC2 + 16 + hh] + xpS[r64 + 16] + gpS[r64 + 16];
            float gv = Cs[row * LDC2 + 32 + hh] + xpS[r64 + 32] + gpS[r64 + 32];
            float ov = Cs[row * LDC2 + 48 + hh] + xpS[r64 + 48] + gpS[r64 + 48];
            iv = 1.f / (1.f + __expf(-iv));
            fv = 1.f / (1.f + __expf(-fv));
            ov = 1.f / (1.f + __expf(-ov));
            gv = tanhf(gv);
            int ci = row * 16 + hh;
            float cn = fv * ccS[ci] + iv * gv;
            float hn = ov * tanhf(cn);
            ccS[ci] = cn;
            bf16 hb = __float2bfloat16(hn);
            int hidx = b * HH + h0 + hh;
            g_hbuf_bf[(t + 1) & 1][hidx] = hb;
            g_hall_bf[(size_t)(t * BB + b) * HH + h0 + hh] = hb;
        }
        __syncthreads();
        __threadfence();
        if (tid == 0) {
            int v = atomicAdd(&g_barcnt2[grp], 1);
            if (v == GRPBLK - 1) {
                atomicExch(&g_barcnt2[grp], 0);
                __threadfence();
                atomicExch(&g_barflag2[grp], t + 1);
            } else {
                while (atomicAdd(&g_barflag2[grp], 0) < t + 1) { __nanosleep(32); }
                __threadfence();
            }
        }
        __syncthreads();
    }
}

// ---- packed vocab projection (wmma): logits -> out + rowsum of exp ----
__global__ __launch_bounds__(256, 2) void k_out1(const float* __restrict__ bout,
                                                 float* __restrict__ out) {
    extern __shared__ bf16 dsm[];
    int tid = threadIdx.x;
    int m0 = blockIdx.y * 128;
    int ntot = g_ntot;
    if (m0 >= ntot) return;
    int n0 = blockIdx.x * 128;
    int srow = tid >> 1;
    int wp = tid >> 5, wm = wp & 3, wn = wp >> 2;
    int tb = g_rowmap[m0 + srow];
    const bf16* arow = g_hall_bf + (size_t)tb * HH;
    int nb = n0 + srow;
    const bf16* brow = g_Wout_bf + (size_t)(nb < VV ? nb : VV - 1) * HH;
    FragC c[2][4];
    FRAG_INIT(c);
    gemm_bf16(arow, brow, dsm, dsm + NSTG * BUFB, c, tid);
    float* Cs = (float*)dsm;
    FRAG_TO_CS(c, Cs, wm, wn);
    __syncthreads();

    int row = tid >> 1, cb = (tid & 1) * 64;
    int r = m0 + row;
    if (r < ntot) {
        int tb2 = g_rowmap[r];
        int t = tb2 >> 8, b = tb2 & 255;
        size_t obase = ((size_t)b * ML + t) * VV;
        float psum = 0.f;
        #pragma unroll
        for (int q = 0; q < 16; q++) {
            int n = n0 + cb + q * 4;
            if (n < VV) {
                float4 cv = *(const float4*)&Cs[row * LDC + cb + q * 4];
                float4 bo = *(const float4*)(bout + n);
                float4 v;
                v.x = cv.x + bo.x; v.y = cv.y + bo.y;
                v.z = cv.z + bo.z; v.w = cv.w + bo.w;
                *(float4*)(out + obase + n) = v;
                psum += __expf(v.x) + __expf(v.y) + __expf(v.z) + __expf(v.w);
            }
        }
        atomicAdd(&g_rowsum[tb2], psum);
    }
}

// ---- final: full-output pass; zeros inactive/pad, log-softmax for active ----
__global__ __launch_bounds__(256) void k_out2(float* __restrict__ out) {
    long long idx = (long long)blockIdx.x * 256 + threadIdx.x;
    const int perRow = VV / 4;
    const long long TOT = (long long)BB * ML * perRow;
    if (idx >= TOT) return;
    int r = (int)(idx / perRow);
    int v4 = (int)(idx % perRow);
    int b = r / ML, t = r - b * ML;
    size_t p = (size_t)r * VV + v4 * 4;
    bool active = (t < TT) && (b < g_cnt[t]);
    float4 o = make_float4(0.f, 0.f, 0.f, 0.f);
    if (active) {
        float ls = logf(g_rowsum[t * BB + b]);
        float4 lv = *(const float4*)(out + p);
        o.x = lv.x - ls; o.y = lv.y - ls; o.z = lv.z - ls; o.w = lv.w - ls;
    }
    *(float4*)(out + p) = o;
}

// ---------------- launch ----------------
extern "C" void kernel_launch(void* const* d_in, const int* in_sizes, int n_in,
                              void* d_out, int out_size) {
    const float* gimg = (const float*)d_in[0];
    const int*   w    = (const int*)d_in[1];
    const int*   cap  = (const int*)d_in[2];
    const float* emb  = (const float*)d_in[3];
    const float* Wih  = (const float*)d_in[4];
    const float* Whh  = (const float*)d_in[5];
    const float* bih  = (const float*)d_in[6];
    const float* bhh  = (const float*)d_in[7];
    const float* Wout = (const float*)d_in[8];
    const float* bout = (const float*)d_in[9];
    float* out = (float*)d_out;

    static int attr_done = 0;
    if (!attr_done) {
        cudaFuncSetAttribute(k_proj,  cudaFuncAttributeMaxDynamicSharedMemorySize, DSMEM_BYTES);
        cudaFuncSetAttribute(k_steps, cudaFuncAttributeMaxDynamicSharedMemorySize, DSMEM_STEPS);
        cudaFuncSetAttribute(k_out1,  cudaFuncAttributeMaxDynamicSharedMemorySize, DSMEM_BYTES);
        attr_done = 1;
    }

    k_cvt<<<(int)((N_CVT2 + 255) / 256), 256>>>(Wih, Whh, Wout, emb, gimg);
    k_prep<<<1, 256>>>(w, cap, out, (long long)out_size);
    k_proj<<<dim3(16, 62), 256, DSMEM_BYTES>>>(w, bih, bhh);
    k_steps<<<dim3(32, 2), 256, DSMEM_STEPS>>>();
    k_out1<<<dim3(79, 60), 256, DSMEM_BYTES>>>(bout, out);
    long long tot = (long long)BB * ML * (VV / 4);
    k_out2<<<(int)((tot + 255) / 256), 256>>>(out);
}

// round 14
// speedup vs baseline: 1.3408x; 1.1894x over previous
#include <cuda_runtime.h>
#include <cuda_bf16.h>
#include <mma.h>
#include <math.h>
#include <stdint.h>

using namespace nvcuda;

// Problem constants
#define BB 256
#define TT 30
#define ML 31
#define VV 10000
#define HH 512
#define G4 2048            // 4*H
#define NROWS 7680         // TT*BB
#define BKB 64             // K-chunk (bf16 elems)
#define LDAB 72            // shared lda in bf16 elems (64 + 8 pad) -> 144B rows
#define LDC 132            // shared C ld (floats, 128 + 4 pad)
#define LDC2 68            // shared C ld for 64-wide tiles
#define BUFB (128 * LDAB)  // bf16 elems per A stage buffer (9216)
#define NSTG 3             // pipeline stages (big GEMMs)
#define DSMEM_BYTES (NSTG * 2 * BUFB * 2)          // 110592 B (128x128 GEMMs)
// k_steps v5: 64-row b-groups. A: 3 x ACH2; B resident: 8 x BCH; float tiles.
#define ACH2 (64 * LDAB)   // 4608 bf16 (A stage, 64 rows)
#define BCH (64 * LDAB)    // 4608 bf16 (B chunk, 64 gate rows)
#define NCHUNK 8
#define FS_GP 0            // float offsets within float region
#define FS_XP 4096
#define FS_CC 8192
#define DSMEM_STEPS ((3 * ACH2 + NCHUNK * BCH) * 2 + (4096 + 4096 + 1024) * 4)  // 138240 B
#define GRPBLK 32          // blocks per barrier group
#define NBG 4              // number of b-groups
#define BROWS 64           // rows per b-group

typedef __nv_bfloat16 bf16;

// ---------------- device scratch ----------------
__device__ int   g_order[BB];
__device__ int   g_declen[BB];
__device__ int   g_cnt[TT];
__device__ int   g_rowmap[NROWS];   // packed active row -> t*256+b
__device__ int   g_ntot;            // number of active rows
__device__ float g_gp[BB * G4];     // gimg proj + bih + bhh
__device__ float g_xp[(size_t)NROWS * G4];       // emb-proj only (raw)
__device__ float g_rowsum[NROWS];
__device__ int   g_barcnt2[NBG];
__device__ int   g_barflag2[NBG];
// bf16 operand copies
__device__ bf16  g_Wih_bf[G4 * 1024];
__device__ bf16  g_Whh_bf[G4 * HH];
__device__ bf16  g_Wout_bf[VV * HH];
__device__ bf16  g_emb_bf[VV * HH];
__device__ bf16  g_gimg_bf[BB * HH];
__device__ bf16  g_hbuf_bf[2][BB * HH];
__device__ bf16  g_hall_bf[(size_t)NROWS * HH];

typedef wmma::fragment<wmma::matrix_a, 16, 16, 16, bf16, wmma::row_major> FragA;
typedef wmma::fragment<wmma::matrix_b, 16, 16, 16, bf16, wmma::col_major> FragB;
typedef wmma::fragment<wmma::accumulator, 16, 16, 16, float> FragC;

__device__ __forceinline__ void cp16(void* s, const void* g) {
    unsigned d = (unsigned)__cvta_generic_to_shared(s);
    asm volatile("cp.async.cg.shared.global [%0], [%1], 16;" :: "r"(d), "l"(g));
}

// ---- 3-stage pipelined bf16 GEMM: C[128x128] += A[128x512] * B[128x512]^T ----
__device__ __forceinline__ void gemm_bf16(const bf16* arow, const bf16* brow,
                                          bf16* As, bf16* Bs,
                                          FragC (&c)[2][4], int tid) {
    int wp = tid >> 5, wm = wp & 3, wn = wp >> 2;
    int srow = tid >> 1, sc = (tid & 1) * 32;
    bf16* asd = As + srow * LDAB + sc;
    bf16* bsd = Bs + srow * LDAB + sc;
    const bf16* ag = arow + sc;
    const bf16* bg = brow + sc;
    #pragma unroll
    for (int q = 0; q < 32; q += 8) { cp16(asd + q, ag + q); cp16(bsd + q, bg + q); }
    asm volatile("cp.async.commit_group;");
    #pragma unroll
    for (int q = 0; q < 32; q += 8) {
        cp16(asd + BUFB + q, ag + BKB + q);
        cp16(bsd + BUFB + q, bg + BKB + q);
    }
    asm volatile("cp.async.commit_group;");
    int buf = 0;
    #pragma unroll 1
    for (int k0 = 0; k0 < HH; k0 += BKB) {
        if (k0 + BKB < HH) asm volatile("cp.async.wait_group 1;" ::: "memory");
        else               asm volatile("cp.async.wait_group 0;" ::: "memory");
        __syncthreads();
        if (k0 + 2 * BKB < HH) {
            int nb = buf + 2; if (nb >= NSTG) nb -= NSTG;
            #pragma unroll
            for (int q = 0; q < 32; q += 8) {
                cp16(asd + nb * BUFB + q, ag + k0 + 2 * BKB + q);
                cp16(bsd + nb * BUFB + q, bg + k0 + 2 * BKB + q);
            }
            asm volatile("cp.async.commit_group;");
        }
        bf16* Ab = As + buf * BUFB;
        bf16* Bb = Bs + buf * BUFB;
        #pragma unroll
        for (int kk = 0; kk < BKB; kk += 16) {
            FragA a0, a1; FragB bf[4];
            wmma::load_matrix_sync(a0, &Ab[(wm * 32)      * LDAB + kk], LDAB);
            wmma::load_matrix_sync(a1, &Ab[(wm * 32 + 16) * LDAB + kk], LDAB);
            #pragma unroll
            for (int j = 0; j < 4; j++)
                wmma::load_matrix_sync(bf[j], &Bb[(wn * 64 + j * 16) * LDAB + kk], LDAB);
            #pragma unroll
            for (int j = 0; j < 4; j++) {
                wmma::mma_sync(c[0][j], a0, bf[j], c[0][j]);
                wmma::mma_sync(c[1][j], a1, bf[j], c[1][j]);
            }
        }
        buf = (buf == NSTG - 1) ? 0 : buf + 1;
    }
    __syncthreads();
}

#define FRAG_INIT(c)                                     \
    _Pragma("unroll")                                    \
    for (int i = 0; i < 2; i++)                          \
        _Pragma("unroll")                                \
        for (int j = 0; j < 4; j++) wmma::fill_fragment(c[i][j], 0.f);

#define FRAG_TO_CS(c, Cs, wm, wn)                                                  \
    _Pragma("unroll")                                                              \
    for (int i = 0; i < 2; i++)                                                    \
        _Pragma("unroll")                                                          \
        for (int j = 0; j < 4; j++)                                                \
            wmma::store_matrix_sync(&Cs[(wm * 32 + i * 16) * LDC + wn * 64 + j * 16], \
                                    c[i][j], LDC, wmma::mem_row_major);

// ---------------- fp32 -> bf16 conversion + state init (merged) ----------------
#define N_WIH (G4 * 1024)
#define N_WHH (G4 * HH)
#define N_WOUT (VV * HH)
#define N_EMB (VV * HH)
#define N_GIMG (BB * HH)
#define N_CVT2 ((N_WIH + N_WHH + N_WOUT + N_EMB + N_GIMG) / 2)

__global__ __launch_bounds__(256) void k_cvt(const float* __restrict__ Wih,
                                             const float* __restrict__ Whh,
                                             const float* __restrict__ Wout,
                                             const float* __restrict__ emb,
                                             const float* __restrict__ gimg) {
    long long i2 = (long long)blockIdx.x * 256 + threadIdx.x;
    // merged init work
    if (i2 < BB * HH) {
        g_hbuf_bf[0][i2] = __float2bfloat16(0.f);
        g_hbuf_bf[1][i2] = __float2bfloat16(0.f);
    }
    if (i2 < NROWS) g_rowsum[i2] = 0.f;
    if (i2 < NBG) { g_barcnt2[i2] = 0; g_barflag2[i2] = 0; }
    if (i2 >= N_CVT2) return;
    long long i = i2 * 2;
    const float* src; bf16* dst; long long off;
    if (i < N_WIH)                       { src = Wih;  dst = g_Wih_bf;  off = i; }
    else if (i < (long long)N_WIH + N_WHH) { src = Whh;  dst = g_Whh_bf;  off = i - N_WIH; }
    else if (i < (long long)N_WIH + N_WHH + N_WOUT)
                                         { src = Wout; dst = g_Wout_bf; off = i - N_WIH - N_WHH; }
    else if (i < (long long)N_WIH + N_WHH + N_WOUT + N_EMB)
                                         { src = emb;  dst = g_emb_bf;  off = i - N_WIH - N_WHH - N_WOUT; }
    else                                 { src = gimg; dst = g_gimg_bf; off = i - N_WIH - N_WHH - N_WOUT - N_EMB; }
    float2 v = *(const float2*)(src + off);
    __nv_bfloat162 o = __floats2bfloat162_rn(v.x, v.y);
    *(__nv_bfloat162*)(dst + off) = o;
}

// ---------------- prep: sort + targets + packed row map ----------------
__global__ void k_prep(const int* __restrict__ w, const int* __restrict__ cap,
                       float* __restrict__ out, long long out_size) {
    __shared__ int lens[BB];
    __shared__ int off[TT + 1];
    int i = threadIdx.x;
    lens[i] = cap[i];
    __syncthreads();
    int li = lens[i];
    int rank = 0;
    #pragma unroll 8
    for (int j = 0; j < BB; j++) {
        int lj = lens[j];
        rank += (lj > li) || (lj == li && j < i);
    }
    g_order[rank]  = i;
    g_declen[rank] = li - 1;
    __syncthreads();

    if (i < TT) {
        int c = 0;
        for (int j = 0; j < BB; j++) c += (g_declen[j] > i);
        g_cnt[i] = c;
    }
    __syncthreads();
    if (i == 0) {
        int s = 0;
        for (int t = 0; t < TT; t++) { off[t] = s; s += g_cnt[t]; }
        off[TT] = s;
        g_ntot = s;
    }
    __syncthreads();
    for (int t = 0; t < TT; t++) {
        int c = g_cnt[t];
        for (int b = i; b < c; b += 256) g_rowmap[off[t] + b] = t * 256 + b;
    }
    for (int r = off[TT] + i; r < NROWS; r += 256) g_rowmap[r] = 0;

    long long PRED = (long long)BB * ML * VV;
    if (out_size >= PRED + (long long)BB * TT + BB) {
        int src = g_order[i];
        for (int k = 0; k < TT; k++)
            out[PRED + (long long)i * TT + k] = (float)w[src * ML + k + 1];
        out[PRED + (long long)BB * TT + i] = (float)g_declen[i];
    }
}

// ---- union projection kernel: y<60 -> packed emb proj (raw xp),
//      y>=60 -> image proj + biases (gp). ----
__global__ __launch_bounds__(256, 2) void k_proj(const int* __restrict__ w,
                                                 const float* __restrict__ bih,
                                                 const float* __restrict__ bhh) {
    extern __shared__ bf16 dsm[];
    int tid = threadIdx.x;
    int srow = tid >> 1;
    int wp = tid >> 5, wm = wp & 3, wn = wp >> 2;
    int n0 = blockIdx.x * 128;

    if (blockIdx.y >= 60) {
        int m0 = (blockIdx.y - 60) * 128;
        const bf16* arow = g_gimg_bf + (size_t)g_order[m0 + srow] * HH;
        const bf16* brow = g_Wih_bf + (size_t)(n0 + srow) * 1024;
        FragC c[2][4];
        FRAG_INIT(c);
        gemm_bf16(arow, brow, dsm, dsm + NSTG * BUFB, c, tid);
        float* Cs = (float*)dsm;
        FRAG_TO_CS(c, Cs, wm, wn);
        __syncthreads();
        int row = tid >> 1, cb = (tid & 1) * 64;
        int b = m0 + row;
        #pragma unroll
        for (int q = 0; q < 16; q++) {
            int n = n0 + cb + q * 4;
            float4 cv = *(const float4*)&Cs[row * LDC + cb + q * 4];
            float4 b1 = *(const float4*)(bih + n);
            float4 b2 = *(const float4*)(bhh + n);
            float4 v;
            v.x = cv.x + b1.x + b2.x;
            v.y = cv.y + b1.y + b2.y;
            v.z = cv.z + b1.z + b2.z;
            v.w = cv.w + b1.w + b2.w;
            *(float4*)(g_gp + (size_t)b * G4 + n) = v;
        }
        return;
    }

    int m0 = blockIdx.y * 128;
    int ntot = g_ntot;
    if (m0 >= ntot) return;
    int tb = g_rowmap[m0 + srow];
    int t_r = tb >> 8, b_r = tb & 255;
    int word = w[g_order[b_r] * ML + t_r];
    const bf16* arow = g_emb_bf + (size_t)word * HH;
    const bf16* brow = g_Wih_bf + (size_t)(n0 + srow) * 1024 + 512;
    FragC c[2][4];
    FRAG_INIT(c);
    gemm_bf16(arow, brow, dsm, dsm + NSTG * BUFB, c, tid);
    float* Cs = (float*)dsm;
    FRAG_TO_CS(c, Cs, wm, wn);
    __syncthreads();
    int row = tid >> 1, cb = (tid & 1) * 64;
    int r = m0 + row;
    if (r < ntot) {
        int tb2 = g_rowmap[r];
        size_t xb = (size_t)tb2 * G4;
        #pragma unroll
        for (int q = 0; q < 16; q++) {
            int n = n0 + cb + q * 4;
            *(float4*)(g_xp + xb + n) = *(const float4*)&Cs[row * LDC + cb + q * 4];
        }
    }
}

// ---- persistent recurrent kernel v5: 4 independent 64-row b-groups x 32 blocks.
//      C tile 64b x 64 gate-cols; 3-stage A, resident B, smem gp/xp/cc. ----
__global__ __launch_bounds__(256) void k_steps() {
    extern __shared__ bf16 dsm[];
    bf16* Af = dsm;                          // 3 x ACH2
    bf16* Br = dsm + 3 * ACH2;               // 8 x BCH
    float* fsm = (float*)(dsm + 3 * ACH2 + NCHUNK * BCH);
    float* gpS = fsm + FS_GP;                // 64 x 64
    float* xpS = fsm + FS_XP;                // 64 x 64
    float* ccS = fsm + FS_CC;                // 64 x 16
    float* Cs = (float*)dsm;                 // aliases Af after bursts (64xLDC2)
    int tid = threadIdx.x;
    int h0 = blockIdx.x * 16;                // 32 h-tiles
    int grp = blockIdx.y;                    // 0..3
    int b0 = grp * BROWS;
    int wp = tid >> 5, wm = wp & 1, wn = wp >> 1;  // warp tile: 32 rows x 16 cols
    int srowA = tid >> 2, scA = (tid & 3) * 16;    // A stage: 64 rows x 64 cols
    int rowX = tid >> 2, qX = tid & 3;             // float tiles: 64 rows x 4 quarters

    // ---- one-time staging: resident B (W_hh) + gp tile; zero cc ----
    {
        int row4 = tid >> 2, c16 = (tid & 3) * 16;
        int gate = row4 >> 4, hh_s = row4 & 15;
        const bf16* bg = g_Whh_bf + (size_t)(gate * 512 + h0 + hh_s) * HH;
        #pragma unroll
        for (int ch = 0; ch < NCHUNK; ch++) {
            bf16* d = Br + ch * BCH + row4 * LDAB + c16;
            const bf16* s = bg + ch * BKB + c16;
            cp16(d, s); cp16(d + 8, s + 8);
        }
        // gp: row rowX, gate qX, 16 floats
        const float* s = g_gp + (size_t)(b0 + rowX) * G4 + qX * 512 + h0;
        float* d = gpS + rowX * 64 + qX * 16;
        cp16(d, s); cp16(d + 4, s + 4); cp16(d + 8, s + 8); cp16(d + 12, s + 12);
        asm volatile("cp.async.commit_group;");
        asm volatile("cp.async.wait_group 0;" ::: "memory");
        #pragma unroll
        for (int i = 0; i < 4; i++) ccS[tid * 4 + i] = 0.f;
        __syncthreads();
    }

    for (int t = 0; t < TT; t++) {
        int cnt = g_cnt[t];
        if (cnt <= b0) break;                // whole group exits together
        FragC c[2];
        wmma::fill_fragment(c[0], 0.f);
        wmma::fill_fragment(c[1], 0.f);
        const bf16* ag = g_hbuf_bf[t & 1] + (size_t)(b0 + srowA) * HH + scA;
        bf16* asd = Af + srowA * LDAB + scA;
        // prologue: chunk0 -> buf0 (G0), chunk1 -> buf1 (G1)
        cp16(asd, ag); cp16(asd + 8, ag + 8);
        asm volatile("cp.async.commit_group;");
        cp16(asd + ACH2, ag + BKB); cp16(asd + ACH2 + 8, ag + BKB + 8);
        asm volatile("cp.async.commit_group;");

        #pragma unroll 1
        for (int ch = 0; ch < NCHUNK; ch++) {
            if (ch < NCHUNK - 1) asm volatile("cp.async.wait_group 1;" ::: "memory");
            else                 asm volatile("cp.async.wait_group 0;" ::: "memory");
            __syncthreads();
            if (ch < NCHUNK - 2) {
                int dch = ch + 2;
                int dbuf = dch; while (dbuf >= 3) dbuf -= 3;
                const bf16* s = ag + dch * BKB;
                bf16* d = asd + dbuf * ACH2;
                cp16(d, s); cp16(d + 8, s + 8);
                if (ch == 0) {
                    // xp(t) prefetch rides G2; retired by chunk-2's wait
                    const float* xs = g_xp + (size_t)(t * BB + b0 + rowX) * G4
                                      + qX * 512 + h0;
                    float* xd = xpS + rowX * 64 + qX * 16;
                    cp16(xd, xs); cp16(xd + 4, xs + 4);
                    cp16(xd + 8, xs + 8); cp16(xd + 12, xs + 12);
                }
                asm volatile("cp.async.commit_group;");
            }
            int cbuf = ch; while (cbuf >= 3) cbuf -= 3;
            bf16* Ab = Af + cbuf * ACH2;
            bf16* Bb = Br + ch * BCH;
            #pragma unroll
            for (int kk = 0; kk < BKB; kk += 16) {
                FragA a0, a1; FragB bf0;
                wmma::load_matrix_sync(a0, &Ab[(wm * 32)      * LDAB + kk], LDAB);
                wmma::load_matrix_sync(a1, &Ab[(wm * 32 + 16) * LDAB + kk], LDAB);
                wmma::load_matrix_sync(bf0, &Bb[(wn * 16) * LDAB + kk], LDAB);
                wmma::mma_sync(c[0], a0, bf0, c[0]);
                wmma::mma_sync(c[1], a1, bf0, c[1]);
            }
        }
        __syncthreads();   // all warps done reading Af before Cs overwrite
        wmma::store_matrix_sync(&Cs[(wm * 32)      * LDC2 + wn * 16], c[0], LDC2,
                                wmma::mem_row_major);
        wmma::store_matrix_sync(&Cs[(wm * 32 + 16) * LDC2 + wn * 16], c[1], LDC2,
                                wmma::mem_row_major);
        __syncthreads();
        // LSTM elementwise: 64 rows x 16 h, all inputs in smem
        #pragma unroll
        for (int it = 0; it < 4; it++) {
            int p = it * 256 + tid;            // 0..1023
            int row = p >> 4;
            int hh = p & 15;
            int b = b0 + row;
            if (b >= cnt) continue;
            int r64 = row * 64 + hh;
            float iv = Cs[row * LDC2 + 0  + hh] + xpS[r64]      + gpS[r64];
            float fv = Cs[row * LDC2 + 16 + hh] + xpS[r64 + 16] + gpS[r64 + 16];
            float gv = Cs[row * LDC2 + 32 + hh] + xpS[r64 + 32] + gpS[r64 + 32];
            float ov = Cs[row * LDC2 + 48 + hh] + xpS[r64 + 48] + gpS[r64 + 48];
            iv = 1.f / (1.f + __expf(-iv));
            fv = 1.f / (1.f + __expf(-fv));
            ov = 1.f / (1.f + __expf(-ov));
            gv = tanhf(gv);
            int ci = row * 16 + hh;
            float cn = fv * ccS[ci] + iv * gv;
            float hn = ov * tanhf(cn);
            ccS[ci] = cn;
            bf16 hb = __float2bfloat16(hn);
            int hidx = b * HH + h0 + hh;
            g_hbuf_bf[(t + 1) & 1][hidx] = hb;
            g_hall_bf[(size_t)(t * BB + b) * HH + h0 + hh] = hb;
        }
        __syncthreads();
        __threadfence();
        if (tid == 0) {
            int v = atomicAdd(&g_barcnt2[grp], 1);
            if (v == GRPBLK - 1) {
                atomicExch(&g_barcnt2[grp], 0);
                __threadfence();
                atomicExch(&g_barflag2[grp], t + 1);
            } else {
                while (atomicAdd(&g_barflag2[grp], 0) < t + 1) { __nanosleep(32); }
                __threadfence();
            }
        }
        __syncthreads();
    }
}

// ---- packed vocab projection (wmma): logits -> out + rowsum of exp ----
__global__ __launch_bounds__(256, 2) void k_out1(const float* __restrict__ bout,
                                                 float* __restrict__ out) {
    extern __shared__ bf16 dsm[];
    int tid = threadIdx.x;
    int m0 = blockIdx.y * 128;
    int ntot = g_ntot;
    if (m0 >= ntot) return;
    int n0 = blockIdx.x * 128;
    int srow = tid >> 1;
    int wp = tid >> 5, wm = wp & 3, wn = wp >> 2;
    int tb = g_rowmap[m0 + srow];
    const bf16* arow = g_hall_bf + (size_t)tb * HH;
    int nb = n0 + srow;
    const bf16* brow = g_Wout_bf + (size_t)(nb < VV ? nb : VV - 1) * HH;
    FragC c[2][4];
    FRAG_INIT(c);
    gemm_bf16(arow, brow, dsm, dsm + NSTG * BUFB, c, tid);
    float* Cs = (float*)dsm;
    FRAG_TO_CS(c, Cs, wm, wn);
    __syncthreads();

    int row = tid >> 1, cb = (tid & 1) * 64;
    int r = m0 + row;
    if (r < ntot) {
        int tb2 = g_rowmap[r];
        int t = tb2 >> 8, b = tb2 & 255;
        size_t obase = ((size_t)b * ML + t) * VV;
        float psum = 0.f;
        #pragma unroll
        for (int q = 0; q < 16; q++) {
            int n = n0 + cb + q * 4;
            if (n < VV) {
                float4 cv = *(const float4*)&Cs[row * LDC + cb + q * 4];
                float4 bo = *(const float4*)(bout + n);
                float4 v;
                v.x = cv.x + bo.x; v.y = cv.y + bo.y;
                v.z = cv.z + bo.z; v.w = cv.w + bo.w;
                *(float4*)(out + obase + n) = v;
                psum += __expf(v.x) + __expf(v.y) + __expf(v.z) + __expf(v.w);
            }
        }
        atomicAdd(&g_rowsum[tb2], psum);
    }
}

// ---- final: full-output pass; zeros inactive/pad, log-softmax for active ----
__global__ __launch_bounds__(256) void k_out2(float* __restrict__ out) {
    long long idx = (long long)blockIdx.x * 256 + threadIdx.x;
    const int perRow = VV / 4;
    const long long TOT = (long long)BB * ML * perRow;
    if (idx >= TOT) return;
    int r = (int)(idx / perRow);
    int v4 = (int)(idx % perRow);
    int b = r / ML, t = r - b * ML;
    size_t p = (size_t)r * VV + v4 * 4;
    bool active = (t < TT) && (b < g_cnt[t]);
    float4 o = make_float4(0.f, 0.f, 0.f, 0.f);
    if (active) {
        float ls = logf(g_rowsum[t * BB + b]);
        float4 lv = *(const float4*)(out + p);
        o.x = lv.x - ls; o.y = lv.y - ls; o.z = lv.z - ls; o.w = lv.w - ls;
    }
    *(float4*)(out + p) = o;
}

// ---------------- launch ----------------
extern "C" void kernel_launch(void* const* d_in, const int* in_sizes, int n_in,
                              void* d_out, int out_size) {
    const float* gimg = (const float*)d_in[0];
    const int*   w    = (const int*)d_in[1];
    const int*   cap  = (const int*)d_in[2];
    const float* emb  = (const float*)d_in[3];
    const float* Wih  = (const float*)d_in[4];
    const float* Whh  = (const float*)d_in[5];
    const float* bih  = (const float*)d_in[6];
    const float* bhh  = (const float*)d_in[7];
    const float* Wout = (const float*)d_in[8];
    const float* bout = (const float*)d_in[9];
    float* out = (float*)d_out;

    static int attr_done = 0;
    if (!attr_done) {
        cudaFuncSetAttribute(k_proj,  cudaFuncAttributeMaxDynamicSharedMemorySize, DSMEM_BYTES);
        cudaFuncSetAttribute(k_steps, cudaFuncAttributeMaxDynamicSharedMemorySize, DSMEM_STEPS);
        cudaFuncSetAttribute(k_out1,  cudaFuncAttributeMaxDynamicSharedMemorySize, DSMEM_BYTES);
        attr_done = 1;
    }

    k_cvt<<<(int)((N_CVT2 + 255) / 256), 256>>>(Wih, Whh, Wout, emb, gimg);
    k_prep<<<1, 256>>>(w, cap, out, (long long)out_size);
    k_proj<<<dim3(16, 62), 256, DSMEM_BYTES>>>(w, bih, bhh);
    k_steps<<<dim3(32, NBG), 256, DSMEM_STEPS>>>();
    k_out1<<<dim3(79, 60), 256, DSMEM_BYTES>>>(bout, out);
    long long tot = (long long)BB * ML * (VV / 4);
    k_out2<<<(int)((tot + 255) / 256), 256>>>(out);
}

// round 15
// speedup vs baseline: 1.3826x; 1.0312x over previous
#include <cuda_runtime.h>
#include <cuda_bf16.h>
#include <mma.h>
#include <math.h>
#include <stdint.h>

using namespace nvcuda;

// Problem constants
#define BB 256
#define TT 30
#define ML 31
#define VV 10000
#define HH 512
#define G4 2048            // 4*H
#define NROWS 7680         // TT*BB
#define BKB 64             // K-chunk (bf16 elems)
#define LDAB 72            // shared lda in bf16 elems (64 + 8 pad) -> 144B rows
#define LDC 132            // shared C ld (floats, 128 + 4 pad)
#define LDC3 36            // shared C ld for 32-wide tiles
#define BUFB (128 * LDAB)  // bf16 elems per A stage buffer (9216)
#define NSTG 3             // pipeline stages (big GEMMs)
#define DSMEM_BYTES (NSTG * 2 * BUFB * 2)          // 110592 B (128x128 GEMMs)
// k_steps v6: 64-row b-groups x 64 h-tiles of 8. A: 3 x ACH2; B: 8 x BCH3.
#define ACH2 (64 * LDAB)   // 4608 bf16 (A stage, 64 rows)
#define BCH3 (32 * LDAB)   // 2304 bf16 (B chunk, 32 gate rows)
#define NCHUNK 8
#define FS_GP 0            // float offsets within float region
#define FS_XP 2048
#define FS_CC 4096
#define DSMEM_STEPS ((3 * ACH2 + NCHUNK * BCH3) * 2 + (2048 + 2048 + 512) * 4)  // 82944 B
#define GRPBLK 64          // blocks per barrier group
#define NBG 4              // number of b-groups
#define BROWS 64           // rows per b-group

typedef __nv_bfloat16 bf16;

// ---------------- device scratch ----------------
__device__ int   g_order[BB];
__device__ int   g_declen[BB];
__device__ int   g_cnt[TT];
__device__ int   g_rowmap[NROWS];   // packed active row -> t*256+b
__device__ int   g_ntot;            // number of active rows
__device__ float g_gp[BB * G4];     // gimg proj + bih + bhh
__device__ float g_xp[(size_t)NROWS * G4];       // emb-proj only (raw)
__device__ float g_rowsum[NROWS];
__device__ int   g_barcnt2[NBG];
__device__ int   g_barflag2[NBG];
// bf16 operand copies
__device__ bf16  g_Wih_bf[G4 * 1024];
__device__ bf16  g_Whh_bf[G4 * HH];
__device__ bf16  g_Wout_bf[VV * HH];
__device__ bf16  g_emb_bf[VV * HH];
__device__ bf16  g_gimg_bf[BB * HH];
__device__ bf16  g_hbuf_bf[2][BB * HH];
__device__ bf16  g_hall_bf[(size_t)NROWS * HH];

typedef wmma::fragment<wmma::matrix_a, 16, 16, 16, bf16, wmma::row_major> FragA;
typedef wmma::fragment<wmma::matrix_b, 16, 16, 16, bf16, wmma::col_major> FragB;
typedef wmma::fragment<wmma::accumulator, 16, 16, 16, float> FragC;

__device__ __forceinline__ void cp16(void* s, const void* g) {
    unsigned d = (unsigned)__cvta_generic_to_shared(s);
    asm volatile("cp.async.cg.shared.global [%0], [%1], 16;" :: "r"(d), "l"(g));
}

// ---- 3-stage pipelined bf16 GEMM: C[128x128] += A[128x512] * B[128x512]^T ----
__device__ __forceinline__ void gemm_bf16(const bf16* arow, const bf16* brow,
                                          bf16* As, bf16* Bs,
                                          FragC (&c)[2][4], int tid) {
    int wp = tid >> 5, wm = wp & 3, wn = wp >> 2;
    int srow = tid >> 1, sc = (tid & 1) * 32;
    bf16* asd = As + srow * LDAB + sc;
    bf16* bsd = Bs + srow * LDAB + sc;
    const bf16* ag = arow + sc;
    const bf16* bg = brow + sc;
    #pragma unroll
    for (int q = 0; q < 32; q += 8) { cp16(asd + q, ag + q); cp16(bsd + q, bg + q); }
    asm volatile("cp.async.commit_group;");
    #pragma unroll
    for (int q = 0; q < 32; q += 8) {
        cp16(asd + BUFB + q, ag + BKB + q);
        cp16(bsd + BUFB + q, bg + BKB + q);
    }
    asm volatile("cp.async.commit_group;");
    int buf = 0;
    #pragma unroll 1
    for (int k0 = 0; k0 < HH; k0 += BKB) {
        if (k0 + BKB < HH) asm volatile("cp.async.wait_group 1;" ::: "memory");
        else               asm volatile("cp.async.wait_group 0;" ::: "memory");
        __syncthreads();
        if (k0 + 2 * BKB < HH) {
            int nb = buf + 2; if (nb >= NSTG) nb -= NSTG;
            #pragma unroll
            for (int q = 0; q < 32; q += 8) {
                cp16(asd + nb * BUFB + q, ag + k0 + 2 * BKB + q);
                cp16(bsd + nb * BUFB + q, bg + k0 + 2 * BKB + q);
            }
            asm volatile("cp.async.commit_group;");
        }
        bf16* Ab = As + buf * BUFB;
        bf16* Bb = Bs + buf * BUFB;
        #pragma unroll
        for (int kk = 0; kk < BKB; kk += 16) {
            FragA a0, a1; FragB bf[4];
            wmma::load_matrix_sync(a0, &Ab[(wm * 32)      * LDAB + kk], LDAB);
            wmma::load_matrix_sync(a1, &Ab[(wm * 32 + 16) * LDAB + kk], LDAB);
            #pragma unroll
            for (int j = 0; j < 4; j++)
                wmma::load_matrix_sync(bf[j], &Bb[(wn * 64 + j * 16) * LDAB + kk], LDAB);
            #pragma unroll
            for (int j = 0; j < 4; j++) {
                wmma::mma_sync(c[0][j], a0, bf[j], c[0][j]);
                wmma::mma_sync(c[1][j], a1, bf[j], c[1][j]);
            }
        }
        buf = (buf == NSTG - 1) ? 0 : buf + 1;
    }
    __syncthreads();
}

#define FRAG_INIT(c)                                     \
    _Pragma("unroll")                                    \
    for (int i = 0; i < 2; i++)                          \
        _Pragma("unroll")                                \
        for (int j = 0; j < 4; j++) wmma::fill_fragment(c[i][j], 0.f);

#define FRAG_TO_CS(c, Cs, wm, wn)                                                  \
    _Pragma("unroll")                                                              \
    for (int i = 0; i < 2; i++)                                                    \
        _Pragma("unroll")                                                          \
        for (int j = 0; j < 4; j++)                                                \
            wmma::store_matrix_sync(&Cs[(wm * 32 + i * 16) * LDC + wn * 64 + j * 16], \
                                    c[i][j], LDC, wmma::mem_row_major);

// ---------------- fp32 -> bf16 conversion + state init (merged) ----------------
#define N_WIH (G4 * 1024)
#define N_WHH (G4 * HH)
#define N_WOUT (VV * HH)
#define N_EMB (VV * HH)
#define N_GIMG (BB * HH)
#define N_CVT2 ((N_WIH + N_WHH + N_WOUT + N_EMB + N_GIMG) / 2)

__global__ __launch_bounds__(256) void k_cvt(const float* __restrict__ Wih,
                                             const float* __restrict__ Whh,
                                             const float* __restrict__ Wout,
                                             const float* __restrict__ emb,
                                             const float* __restrict__ gimg) {
    long long i2 = (long long)blockIdx.x * 256 + threadIdx.x;
    if (i2 < BB * HH) {
        g_hbuf_bf[0][i2] = __float2bfloat16(0.f);
        g_hbuf_bf[1][i2] = __float2bfloat16(0.f);
    }
    if (i2 < NROWS) g_rowsum[i2] = 0.f;
    if (i2 < NBG) { g_barcnt2[i2] = 0; g_barflag2[i2] = 0; }
    if (i2 >= N_CVT2) return;
    long long i = i2 * 2;
    const float* src; bf16* dst; long long off;
    if (i < N_WIH)                       { src = Wih;  dst = g_Wih_bf;  off = i; }
    else if (i < (long long)N_WIH + N_WHH) { src = Whh;  dst = g_Whh_bf;  off = i - N_WIH; }
    else if (i < (long long)N_WIH + N_WHH + N_WOUT)
                                         { src = Wout; dst = g_Wout_bf; off = i - N_WIH - N_WHH; }
    else if (i < (long long)N_WIH + N_WHH + N_WOUT + N_EMB)
                                         { src = emb;  dst = g_emb_bf;  off = i - N_WIH - N_WHH - N_WOUT; }
    else                                 { src = gimg; dst = g_gimg_bf; off = i - N_WIH - N_WHH - N_WOUT - N_EMB; }
    float2 v = *(const float2*)(src + off);
    __nv_bfloat162 o = __floats2bfloat162_rn(v.x, v.y);
    *(__nv_bfloat162*)(dst + off) = o;
}

// ---------------- prep: sort + targets + packed row map ----------------
__global__ void k_prep(const int* __restrict__ w, const int* __restrict__ cap,
                       float* __restrict__ out, long long out_size) {
    __shared__ int lens[BB];
    __shared__ int off[TT + 1];
    int i = threadIdx.x;
    lens[i] = cap[i];
    __syncthreads();
    int li = lens[i];
    int rank = 0;
    #pragma unroll 8
    for (int j = 0; j < BB; j++) {
        int lj = lens[j];
        rank += (lj > li) || (lj == li && j < i);
    }
    g_order[rank]  = i;
    g_declen[rank] = li - 1;
    __syncthreads();

    if (i < TT) {
        int c = 0;
        for (int j = 0; j < BB; j++) c += (g_declen[j] > i);
        g_cnt[i] = c;
    }
    __syncthreads();
    if (i == 0) {
        int s = 0;
        for (int t = 0; t < TT; t++) { off[t] = s; s += g_cnt[t]; }
        off[TT] = s;
        g_ntot = s;
    }
    __syncthreads();
    for (int t = 0; t < TT; t++) {
        int c = g_cnt[t];
        for (int b = i; b < c; b += 256) g_rowmap[off[t] + b] = t * 256 + b;
    }
    for (int r = off[TT] + i; r < NROWS; r += 256) g_rowmap[r] = 0;

    long long PRED = (long long)BB * ML * VV;
    if (out_size >= PRED + (long long)BB * TT + BB) {
        int src = g_order[i];
        for (int k = 0; k < TT; k++)
            out[PRED + (long long)i * TT + k] = (float)w[src * ML + k + 1];
        out[PRED + (long long)BB * TT + i] = (float)g_declen[i];
    }
}

// ---- union projection kernel: y<60 -> packed emb proj (raw xp),
//      y>=60 -> image proj + biases (gp). ----
__global__ __launch_bounds__(256, 2) void k_proj(const int* __restrict__ w,
                                                 const float* __restrict__ bih,
                                                 const float* __restrict__ bhh) {
    extern __shared__ bf16 dsm[];
    int tid = threadIdx.x;
    int srow = tid >> 1;
    int wp = tid >> 5, wm = wp & 3, wn = wp >> 2;
    int n0 = blockIdx.x * 128;

    if (blockIdx.y >= 60) {
        int m0 = (blockIdx.y - 60) * 128;
        const bf16* arow = g_gimg_bf + (size_t)g_order[m0 + srow] * HH;
        const bf16* brow = g_Wih_bf + (size_t)(n0 + srow) * 1024;
        FragC c[2][4];
        FRAG_INIT(c);
        gemm_bf16(arow, brow, dsm, dsm + NSTG * BUFB, c, tid);
        float* Cs = (float*)dsm;
        FRAG_TO_CS(c, Cs, wm, wn);
        __syncthreads();
        int row = tid >> 1, cb = (tid & 1) * 64;
        int b = m0 + row;
        #pragma unroll
        for (int q = 0; q < 16; q++) {
            int n = n0 + cb + q * 4;
            float4 cv = *(const float4*)&Cs[row * LDC + cb + q * 4];
            float4 b1 = *(const float4*)(bih + n);
            float4 b2 = *(const float4*)(bhh + n);
            float4 v;
            v.x = cv.x + b1.x + b2.x;
            v.y = cv.y + b1.y + b2.y;
            v.z = cv.z + b1.z + b2.z;
            v.w = cv.w + b1.w + b2.w;
            *(float4*)(g_gp + (size_t)b * G4 + n) = v;
        }
        return;
    }

    int m0 = blockIdx.y * 128;
    int ntot = g_ntot;
    if (m0 >= ntot) return;
    int tb = g_rowmap[m0 + srow];
    int t_r = tb >> 8, b_r = tb & 255;
    int word = w[g_order[b_r] * ML + t_r];
    const bf16* arow = g_emb_bf + (size_t)word * HH;
    const bf16* brow = g_Wih_bf + (size_t)(n0 + srow) * 1024 + 512;
    FragC c[2][4];
    FRAG_INIT(c);
    gemm_bf16(arow, brow, dsm, dsm + NSTG * BUFB, c, tid);
    float* Cs = (float*)dsm;
    FRAG_TO_CS(c, Cs, wm, wn);
    __syncthreads();
    int row = tid >> 1, cb = (tid & 1) * 64;
    int r = m0 + row;
    if (r < ntot) {
        int tb2 = g_rowmap[r];
        size_t xb = (size_t)tb2 * G4;
        #pragma unroll
        for (int q = 0; q < 16; q++) {
            int n = n0 + cb + q * 4;
            *(float4*)(g_xp + xb + n) = *(const float4*)&Cs[row * LDC + cb + q * 4];
        }
    }
}

// ---- persistent recurrent kernel v6: 4 b-groups x 64 h-tiles of 8 = 256 blocks,
//      128 threads, 2 CTAs/SM. C tile 64b x 32 gate-cols; smem gp/xp/cc. ----
__global__ __launch_bounds__(128, 2) void k_steps() {
    extern __shared__ bf16 dsm[];
    bf16* Af = dsm;                          // 3 x ACH2
    bf16* Br = dsm + 3 * ACH2;               // 8 x BCH3
    float* fsm = (float*)(dsm + 3 * ACH2 + NCHUNK * BCH3);
    float* gpS = fsm + FS_GP;                // 64 x 32
    float* xpS = fsm + FS_XP;                // 64 x 32
    float* ccS = fsm + FS_CC;                // 64 x 8
    float* Cs = (float*)dsm;                 // aliases Af after bursts (64xLDC3)
    int tid = threadIdx.x;
    int h0 = blockIdx.x * 8;                 // 64 h-tiles of 8
    int grp = blockIdx.y;                    // 0..3
    int b0 = grp * BROWS;
    int wp = tid >> 5, wm = wp & 1, wn = wp >> 1;  // warp tile: 32 rows x 16 cols
    int srowA = tid >> 1, scA = (tid & 1) * 32;    // A stage: 64 rows x 64 cols
    int rowX = tid >> 1, halfX = tid & 1;          // float tiles: 64 rows x 2 halves

    // ---- one-time staging: resident B (W_hh, 32 rows) + gp tile; zero cc ----
    {
        int row4 = tid >> 2, c16 = (tid & 3) * 16;       // 32 rows x 64 cols
        int gate = row4 >> 3, hh_s = row4 & 7;
        const bf16* bg = g_Whh_bf + (size_t)(gate * 512 + h0 + hh_s) * HH;
        #pragma unroll
        for (int ch = 0; ch < NCHUNK; ch++) {
            bf16* d = Br + ch * BCH3 + row4 * LDAB + c16;
            const bf16* s = bg + ch * BKB + c16;
            cp16(d, s); cp16(d + 8, s + 8);
        }
        // gp: row rowX, gates halfX*2 and halfX*2+1, 8 floats each
        #pragma unroll
        for (int g2 = 0; g2 < 2; g2++) {
            int gate2 = halfX * 2 + g2;
            const float* s = g_gp + (size_t)(b0 + rowX) * G4 + gate2 * 512 + h0;
            float* d = gpS + rowX * 32 + gate2 * 8;
            cp16(d, s); cp16(d + 4, s + 4);
        }
        asm volatile("cp.async.commit_group;");
        asm volatile("cp.async.wait_group 0;" ::: "memory");
        #pragma unroll
        for (int i = 0; i < 4; i++) ccS[tid * 4 + i] = 0.f;
        __syncthreads();
    }

    for (int t = 0; t < TT; t++) {
        int cnt = g_cnt[t];
        if (cnt <= b0) break;                // whole group exits together
        FragC c[2];
        wmma::fill_fragment(c[0], 0.f);
        wmma::fill_fragment(c[1], 0.f);
        const bf16* ag = g_hbuf_bf[t & 1] + (size_t)(b0 + srowA) * HH + scA;
        bf16* asd = Af + srowA * LDAB + scA;
        // prologue: chunk0 -> buf0 (G0), chunk1 -> buf1 (G1); 4 cp16 each
        #pragma unroll
        for (int q = 0; q < 32; q += 8) cp16(asd + q, ag + q);
        asm volatile("cp.async.commit_group;");
        #pragma unroll
        for (int q = 0; q < 32; q += 8) cp16(asd + ACH2 + q, ag + BKB + q);
        asm volatile("cp.async.commit_group;");

        #pragma unroll 1
        for (int ch = 0; ch < NCHUNK; ch++) {
            if (ch < NCHUNK - 1) asm volatile("cp.async.wait_group 1;" ::: "memory");
            else                 asm volatile("cp.async.wait_group 0;" ::: "memory");
            __syncthreads();
            if (ch < NCHUNK - 2) {
                int dch = ch + 2;
                int dbuf = dch; while (dbuf >= 3) dbuf -= 3;
                const bf16* s = ag + dch * BKB;
                bf16* d = asd + dbuf * ACH2;
                #pragma unroll
                for (int q = 0; q < 32; q += 8) cp16(d + q, s + q);
                if (ch == 0) {
                    // xp(t) prefetch rides G2; retired by chunk-2's wait
                    #pragma unroll
                    for (int g2 = 0; g2 < 2; g2++) {
                        int gate2 = halfX * 2 + g2;
                        const float* xs = g_xp + (size_t)(t * BB + b0 + rowX) * G4
                                          + gate2 * 512 + h0;
                        float* xd = xpS + rowX * 32 + gate2 * 8;
                        cp16(xd, xs); cp16(xd + 4, xs + 4);
                    }
                }
                asm volatile("cp.async.commit_group;");
            }
            int cbuf = ch; while (cbuf >= 3) cbuf -= 3;
            bf16* Ab = Af + cbuf * ACH2;
            bf16* Bb = Br + ch * BCH3;
            #pragma unroll
            for (int kk = 0; kk < BKB; kk += 16) {
                FragA a0, a1; FragB bf0;
                wmma::load_matrix_sync(a0, &Ab[(wm * 32)      * LDAB + kk], LDAB);
                wmma::load_matrix_sync(a1, &Ab[(wm * 32 + 16) * LDAB + kk], LDAB);
                wmma::load_matrix_sync(bf0, &Bb[(wn * 16) * LDAB + kk], LDAB);
                wmma::mma_sync(c[0], a0, bf0, c[0]);
                wmma::mma_sync(c[1], a1, bf0, c[1]);
            }
        }
        __syncthreads();   // all warps done reading Af before Cs overwrite
        wmma::store_matrix_sync(&Cs[(wm * 32)      * LDC3 + wn * 16], c[0], LDC3,
                                wmma::mem_row_major);
        wmma::store_matrix_sync(&Cs[(wm * 32 + 16) * LDC3 + wn * 16], c[1], LDC3,
                                wmma::mem_row_major);
        __syncthreads();
        // LSTM elementwise: 64 rows x 8 h, all inputs in smem
        #pragma unroll
        for (int it = 0; it < 4; it++) {
            int p = it * 128 + tid;            // 0..511
            int row = p >> 3;
            int hh = p & 7;
            int b = b0 + row;
            if (b >= cnt) continue;
            int r32 = row * 32 + hh;
            float iv = Cs[row * LDC3 + 0  + hh] + xpS[r32]      + gpS[r32];
            float fv = Cs[row * LDC3 + 8  + hh] + xpS[r32 + 8]  + gpS[r32 + 8];
            float gv = Cs[row * LDC3 + 16 + hh] + xpS[r32 + 16] + gpS[r32 + 16];
            float ov = Cs[row * LDC3 + 24 + hh] + xpS[r32 + 24] + gpS[r32 + 24];
            iv = 1.f / (1.f + __expf(-iv));
            fv = 1.f / (1.f + __expf(-fv));
            ov = 1.f / (1.f + __expf(-ov));
            gv = tanhf(gv);
            int ci = row * 8 + hh;
            float cn = fv * ccS[ci] + iv * gv;
            float hn = ov * tanhf(cn);
            ccS[ci] = cn;
            bf16 hb = __float2bfloat16(hn);
            int hidx = b * HH + h0 + hh;
            g_hbuf_bf[(t + 1) & 1][hidx] = hb;
            g_hall_bf[(size_t)(t * BB + b) * HH + h0 + hh] = hb;
        }
        __syncthreads();
        __threadfence();
        if (tid == 0) {
            int v = atomicAdd(&g_barcnt2[grp], 1);
            if (v == GRPBLK - 1) {
                atomicExch(&g_barcnt2[grp], 0);
                __threadfence();
                atomicExch(&g_barflag2[grp], t + 1);
            } else {
                while (atomicAdd(&g_barflag2[grp], 0) < t + 1) { __nanosleep(32); }
                __threadfence();
            }
        }
        __syncthreads();
    }
}

// ---- packed vocab projection (wmma): logits -> out + rowsum of exp ----
__global__ __launch_bounds__(256, 2) void k_out1(const float* __restrict__ bout,
                                                 float* __restrict__ out) {
    extern __shared__ bf16 dsm[];
    int tid = threadIdx.x;
    int m0 = blockIdx.y * 128;
    int ntot = g_ntot;
    if (m0 >= ntot) return;
    int n0 = blockIdx.x * 128;
    int srow = tid >> 1;
    int wp = tid >> 5, wm = wp & 3, wn = wp >> 2;
    int tb = g_rowmap[m0 + srow];
    const bf16* arow = g_hall_bf + (size_t)tb * HH;
    int nb = n0 + srow;
    const bf16* brow = g_Wout_bf + (size_t)(nb < VV ? nb : VV - 1) * HH;
    FragC c[2][4];
    FRAG_INIT(c);
    gemm_bf16(arow, brow, dsm, dsm + NSTG * BUFB, c, tid);
    float* Cs = (float*)dsm;
    FRAG_TO_CS(c, Cs, wm, wn);
    __syncthreads();

    int row = tid >> 1, cb = (tid & 1) * 64;
    int r = m0 + row;
    if (r < ntot) {
        int tb2 = g_rowmap[r];
        int t = tb2 >> 8, b = tb2 & 255;
        size_t obase = ((size_t)b * ML + t) * VV;
        float psum = 0.f;
        #pragma unroll
        for (int q = 0; q < 16; q++) {
            int n = n0 + cb + q * 4;
            if (n < VV) {
                float4 cv = *(const float4*)&Cs[row * LDC + cb + q * 4];
                float4 bo = *(const float4*)(bout + n);
                float4 v;
                v.x = cv.x + bo.x; v.y = cv.y + bo.y;
                v.z = cv.z + bo.z; v.w = cv.w + bo.w;
                *(float4*)(out + obase + n) = v;
                psum += __expf(v.x) + __expf(v.y) + __expf(v.z) + __expf(v.w);
            }
        }
        atomicAdd(&g_rowsum[tb2], psum);
    }
}

// ---- final: full-output pass; zeros inactive/pad, log-softmax for active ----
__global__ __launch_bounds__(256) void k_out2(float* __restrict__ out) {
    long long idx = (long long)blockIdx.x * 256 + threadIdx.x;
    const int perRow = VV / 4;
    const long long TOT = (long long)BB * ML * perRow;
    if (idx >= TOT) return;
    int r = (int)(idx / perRow);
    int v4 = (int)(idx % perRow);
    int b = r / ML, t = r - b * ML;
    size_t p = (size_t)r * VV + v4 * 4;
    bool active = (t < TT) && (b < g_cnt[t]);
    float4 o = make_float4(0.f, 0.f, 0.f, 0.f);
    if (active) {
        float ls = logf(g_rowsum[t * BB + b]);
        float4 lv = *(const float4*)(out + p);
        o.x = lv.x - ls; o.y = lv.y - ls; o.z = lv.z - ls; o.w = lv.w - ls;
    }
    *(float4*)(out + p) = o;
}

// ---------------- launch ----------------
extern "C" void kernel_launch(void* const* d_in, const int* in_sizes, int n_in,
                              void* d_out, int out_size) {
    const float* gimg = (const float*)d_in[0];
    const int*   w    = (const int*)d_in[1];
    const int*   cap  = (const int*)d_in[2];
    const float* emb  = (const float*)d_in[3];
    const float* Wih  = (const float*)d_in[4];
    const float* Whh  = (const float*)d_in[5];
    const float* bih  = (const float*)d_in[6];
    const float* bhh  = (const float*)d_in[7];
    const float* Wout = (const float*)d_in[8];
    const float* bout = (const float*)d_in[9];
    float* out = (float*)d_out;

    static int attr_done = 0;
    if (!attr_done) {
        cudaFuncSetAttribute(k_proj,  cudaFuncAttributeMaxDynamicSharedMemorySize, DSMEM_BYTES);
        cudaFuncSetAttribute(k_steps, cudaFuncAttributeMaxDynamicSharedMemorySize, DSMEM_STEPS);
        cudaFuncSetAttribute(k_out1,  cudaFuncAttributeMaxDynamicSharedMemorySize, DSMEM_BYTES);
        attr_done = 1;
    }

    k_cvt<<<(int)((N_CVT2 + 255) / 256), 256>>>(Wih, Whh, Wout, emb, gimg);
    k_prep<<<1, 256>>>(w, cap, out, (long long)out_size);
    k_proj<<<dim3(16, 62), 256, DSMEM_BYTES>>>(w, bih, bhh);
    k_steps<<<dim3(64, NBG), 128, DSMEM_STEPS>>>();
    k_out1<<<dim3(79, 60), 256, DSMEM_BYTES>>>(bout, out);
    long long tot = (long long)BB * ML * (VV / 4);
    k_out2<<<(int)((tot + 255) / 256), 256>>>(out);
}